// round 13
// baseline (speedup 1.0000x reference)
#include <cuda_runtime.h>
#include <cuda_bf16.h>
#include <math.h>
#include <stdint.h>

// ---------------------------------------------------------------------------
// Problem constants
// ---------------------------------------------------------------------------
#define NB    4
#define CDIM  128
#define HWP   4096           // 64*64
#define ROWS  (NB * HWP)     // 16384
#define NHEAD 4
#define DH    32
#define KS    7

// Scratch arena layout (floats)
#define OFF_XS    0u
#define OFF_XN    2097152u            // 16384*128
#define OFF_QKV   4194304u            // len 16384*384
#define OFF_T     11010048u           // len 16384*128
#define OFF_NA    13107200u
#define OFF_X2    15204352u
#define OFF_XN2   17301504u
#define OFF_H1    19398656u           // len 16384*512
#define OFF_GSUM  27787264u           // 512
#define SCRATCH_FLOATS 27788288u

__device__ float d_scratch[SCRATCH_FLOATS];

__device__ __forceinline__ float gelu_exact(float x) {
    return 0.5f * x * (1.0f + erff(x * 0.7071067811865476f));
}

__device__ __forceinline__ uint32_t f2tf32(float f) {
    uint32_t r;
    asm("cvt.rna.tf32.f32 %0, %1;" : "=r"(r) : "f"(f));
    return r;
}

__device__ __forceinline__ void mma_tf32(float d[4], const uint32_t a[4], const uint32_t b[2]) {
    asm volatile(
        "mma.sync.aligned.m16n8k8.row.col.f32.tf32.tf32.f32 "
        "{%0,%1,%2,%3},{%4,%5,%6,%7},{%8,%9},{%0,%1,%2,%3};\n"
        : "+f"(d[0]), "+f"(d[1]), "+f"(d[2]), "+f"(d[3])
        : "r"(a[0]), "r"(a[1]), "r"(a[2]), "r"(a[3]), "r"(b[0]), "r"(b[1]));
}

__device__ __forceinline__ void mma_bf16_k16(float d[4], const uint32_t a[4], const uint32_t b[2]) {
    asm volatile(
        "mma.sync.aligned.m16n8k16.row.col.f32.bf16.bf16.f32 "
        "{%0,%1,%2,%3},{%4,%5,%6,%7},{%8,%9},{%0,%1,%2,%3};\n"
        : "+f"(d[0]), "+f"(d[1]), "+f"(d[2]), "+f"(d[3])
        : "r"(a[0]), "r"(a[1]), "r"(a[2]), "r"(a[3]), "r"(b[0]), "r"(b[1]));
}

// pack (lo, hi) floats into bf16x2 (lo in lower 16 bits = lower k index)
__device__ __forceinline__ uint32_t pack_bf16(float lo, float hi) {
    uint32_t r;
    asm("cvt.rn.bf16x2.f32 %0, %1, %2;" : "=r"(r) : "f"(hi), "f"(lo));
    return r;
}

// ---------------------------------------------------------------------------
// Kernel 1: NCHW -> NHWC transpose + LayerNorm1.  32 pixels per block.
// ---------------------------------------------------------------------------
__global__ __launch_bounds__(128)
void k_transpose_ln(const float* __restrict__ x,
                    const float* __restrict__ w, const float* __restrict__ b,
                    float* __restrict__ xs, float* __restrict__ xn,
                    float* __restrict__ gsum)
{
    __shared__ float s[32][129];
    __shared__ float smu[32], srs[32];
    int tid = threadIdx.x;
    if (blockIdx.x == 0) {
        #pragma unroll
        for (int i = 0; i < 4; i++) gsum[tid + i * 128] = 0.f;
    }
    int row0 = blockIdx.x * 32;
    int n  = row0 >> 12;
    int p0 = row0 & 4095;
    int pl = tid & 31;
    int cg = tid >> 5;       // 0..3

    #pragma unroll 4
    for (int it = 0; it < 32; it++) {
        int c = it * 4 + cg;
        s[pl][c] = x[((size_t)(n * CDIM + c) << 12) + p0 + pl];
    }
    __syncthreads();

    if (tid < 32) {
        float sum = 0.f, sq = 0.f;
        #pragma unroll 8
        for (int c = 0; c < CDIM; c++) { float v = s[tid][c]; sum += v; sq += v * v; }
        float mu  = sum * (1.0f / CDIM);
        float var = sq * (1.0f / CDIM) - mu * mu;
        smu[tid] = mu;
        srs[tid] = rsqrtf(var + 1e-5f);
    }
    __syncthreads();

    float wc = w[tid], bc = b[tid];
    #pragma unroll 4
    for (int it = 0; it < 32; it++) {
        float v = s[it][tid];
        size_t o = (size_t)(row0 + it) * CDIM + tid;
        xs[o] = v;
        xn[o] = (v - smu[it]) * srs[it] * wc + bc;
    }
}

// ---------------------------------------------------------------------------
// Epilogue helpers
// ---------------------------------------------------------------------------
#define EPI_NONE 0
#define EPI_GELU 1
#define EPI_OUT  3   // out NCHW = acc+bias + e1(x2)

template<int EPI>
__device__ __forceinline__ void epi_write(float* __restrict__ C, int row, int col,
                                          int N, float v, const float* __restrict__ e1)
{
    if (EPI == EPI_GELU) {
        C[(size_t)row * N + col] = gelu_exact(v);
    } else if (EPI == EPI_NONE) {
        C[(size_t)row * N + col] = v;
    } else { // EPI_OUT: write NCHW
        v += e1[(size_t)row * CDIM + col];
        int bn = row >> 12, p = row & 4095;
        C[((size_t)(bn * CDIM + col) << 12) + p] = v;
    }
}

// ---------------------------------------------------------------------------
// Pipelined bf16 GEMM (m16n8k16): BM=64, BN=64, BK=32, 128 threads.
// ---------------------------------------------------------------------------
template<int EPI>
__global__ __launch_bounds__(128)
void k_mma_bf16(const float* __restrict__ A, const float* __restrict__ B,
                const float* __restrict__ bias, float* __restrict__ C,
                int M, int N, int K, const float* __restrict__ e1)
{
    constexpr int BM = 64, BN = 64, BK = 32;
    __shared__ uint32_t Asp[BM][20];
    __shared__ uint32_t Bsp[BK / 2][72];

    int tid  = threadIdx.x;
    int lane = tid & 31;
    int warp = tid >> 5;
    int wm = warp & 1, wn = warp >> 1;
    int m0 = blockIdx.y * BM, n0 = blockIdx.x * BN;
    int grp = lane >> 2, qk = lane & 3;

    float d[2][4][4];
    #pragma unroll
    for (int mt = 0; mt < 2; mt++)
        #pragma unroll
        for (int nt = 0; nt < 4; nt++)
            #pragma unroll
            for (int i = 0; i < 4; i++) d[mt][nt][i] = 0.f;

    int arow = tid >> 1, kseg = (tid & 1) * 16, apair = (tid & 1) * 8;
    int pr = tid >> 3, bc = (tid & 7) * 8;     // B: pair-row, col base

    float4 pa0, pa1, pa2, pa3, pb0, pb1, pb2, pb3;

#define LDG_TILE(k0) { \
    const float* ap = A + (size_t)(m0 + arow) * K + (k0) + kseg; \
    pa0 = *(const float4*)ap;       pa1 = *(const float4*)(ap + 4); \
    pa2 = *(const float4*)(ap + 8); pa3 = *(const float4*)(ap + 12); \
    const float* bp = B + (size_t)((k0) + 2 * pr) * N + n0 + bc; \
    pb0 = *(const float4*)bp;       pb1 = *(const float4*)(bp + 4); \
    pb2 = *(const float4*)(bp + N); pb3 = *(const float4*)(bp + N + 4); }

#define STS_TILE() { \
    Asp[arow][apair+0]=pack_bf16(pa0.x,pa0.y); Asp[arow][apair+1]=pack_bf16(pa0.z,pa0.w); \
    Asp[arow][apair+2]=pack_bf16(pa1.x,pa1.y); Asp[arow][apair+3]=pack_bf16(pa1.z,pa1.w); \
    Asp[arow][apair+4]=pack_bf16(pa2.x,pa2.y); Asp[arow][apair+5]=pack_bf16(pa2.z,pa2.w); \
    Asp[arow][apair+6]=pack_bf16(pa3.x,pa3.y); Asp[arow][apair+7]=pack_bf16(pa3.z,pa3.w); \
    Bsp[pr][bc+0]=pack_bf16(pb0.x,pb2.x); Bsp[pr][bc+1]=pack_bf16(pb0.y,pb2.y); \
    Bsp[pr][bc+2]=pack_bf16(pb0.z,pb2.z); Bsp[pr][bc+3]=pack_bf16(pb0.w,pb2.w); \
    Bsp[pr][bc+4]=pack_bf16(pb1.x,pb3.x); Bsp[pr][bc+5]=pack_bf16(pb1.y,pb3.y); \
    Bsp[pr][bc+6]=pack_bf16(pb1.z,pb3.z); Bsp[pr][bc+7]=pack_bf16(pb1.w,pb3.w); }

#define MMA_TILE() { \
    _Pragma("unroll") \
    for (int ks = 0; ks < 2; ks++) { \
        int pb8 = ks * 8; \
        uint32_t af[2][4], bf[4][2]; \
        _Pragma("unroll") \
        for (int mt = 0; mt < 2; mt++) { \
            int r = wm * 32 + mt * 16 + grp; \
            af[mt][0] = Asp[r][pb8 + qk];     af[mt][1] = Asp[r + 8][pb8 + qk]; \
            af[mt][2] = Asp[r][pb8 + qk + 4]; af[mt][3] = Asp[r + 8][pb8 + qk + 4]; \
        } \
        _Pragma("unroll") \
        for (int nt = 0; nt < 4; nt++) { \
            int cidx = wn * 32 + nt * 8 + grp; \
            bf[nt][0] = Bsp[pb8 + qk][cidx]; bf[nt][1] = Bsp[pb8 + qk + 4][cidx]; \
        } \
        _Pragma("unroll") \
        for (int mt = 0; mt < 2; mt++) \
            _Pragma("unroll") \
            for (int nt = 0; nt < 4; nt++) \
                mma_bf16_k16(d[mt][nt], af[mt], bf[nt]); \
    } }

    LDG_TILE(0);
    STS_TILE();
    __syncthreads();
    for (int k0 = BK; k0 < K; k0 += BK) {
        LDG_TILE(k0);
        MMA_TILE();
        __syncthreads();
        STS_TILE();
        __syncthreads();
    }
    MMA_TILE();

#undef LDG_TILE
#undef STS_TILE
#undef MMA_TILE

    #pragma unroll
    for (int mt = 0; mt < 2; mt++) {
        int rbase = m0 + wm * 32 + mt * 16 + grp;
        #pragma unroll
        for (int nt = 0; nt < 4; nt++) {
            int cbase = n0 + wn * 32 + nt * 8 + 2 * qk;
            float b0 = bias[cbase], b1 = bias[cbase + 1];
            epi_write<EPI>(C, rbase,     cbase,     N, d[mt][nt][0] + b0, e1);
            epi_write<EPI>(C, rbase,     cbase + 1, N, d[mt][nt][1] + b1, e1);
            epi_write<EPI>(C, rbase + 8, cbase,     N, d[mt][nt][2] + b0, e1);
            epi_write<EPI>(C, rbase + 8, cbase + 1, N, d[mt][nt][3] + b1, e1);
        }
    }
}

// ---------------------------------------------------------------------------
// Fused conv1 + GELU + conv2 + spatial-mean.  BM=32 rows/block, 128 threads,
// grid 512 (2 waves) — was 64 rows / grid 256 (latency-bound single wave).
// ---------------------------------------------------------------------------
__global__ __launch_bounds__(128)
void k_conv(const float* __restrict__ xn,
            const float* __restrict__ w1, const float* __restrict__ b1,
            const float* __restrict__ w2, const float* __restrict__ b2,
            float* __restrict__ tout, float* __restrict__ gsum)
{
    __shared__ uint32_t As[32][36];
    __shared__ uint32_t Bs1[32][40];
    __shared__ uint32_t St1[32][36];
    __shared__ uint32_t Bs2[32][136];

    int tid  = threadIdx.x;
    int lane = tid & 31;
    int warp = tid >> 5;
    int grp = lane >> 2, qk = lane & 3;
    int wm = warp & 1, wn = warp >> 1;
    int m0 = blockIdx.x * 32;

    // cache conv2_w (32 x 128) in smem once
    {
        int r = tid >> 2, c0 = (tid & 3) * 32;
        #pragma unroll
        for (int i = 0; i < 8; i++) {
            float4 v = *(const float4*)(w2 + (size_t)r * 128 + c0 + i * 4);
            Bs2[r][c0 + i * 4 + 0] = f2tf32(v.x);
            Bs2[r][c0 + i * 4 + 1] = f2tf32(v.y);
            Bs2[r][c0 + i * 4 + 2] = f2tf32(v.z);
            Bs2[r][c0 + i * 4 + 3] = f2tf32(v.w);
        }
    }

    // ---- stage 1: t1 = xn @ w1 (32x32, K=128). Warp tile 16x16 ----
    float acc1[2][4];
    #pragma unroll
    for (int nt = 0; nt < 2; nt++)
        #pragma unroll
        for (int i = 0; i < 4; i++) acc1[nt][i] = 0.f;

    int arow = tid >> 2, kseg = (tid & 3) * 8;
    int b1row = tid >> 2, b1col = (tid & 3) * 8;

    for (int k0 = 0; k0 < 128; k0 += 32) {
        const float* ap = xn + (size_t)(m0 + arow) * CDIM + k0 + kseg;
        #pragma unroll
        for (int i = 0; i < 2; i++) {
            float4 v = *(const float4*)(ap + i * 4);
            As[arow][kseg + i * 4 + 0] = f2tf32(v.x);
            As[arow][kseg + i * 4 + 1] = f2tf32(v.y);
            As[arow][kseg + i * 4 + 2] = f2tf32(v.z);
            As[arow][kseg + i * 4 + 3] = f2tf32(v.w);
        }
        const float* bp = w1 + (size_t)(k0 + b1row) * 32 + b1col;
        #pragma unroll
        for (int i = 0; i < 2; i++) {
            float4 v = *(const float4*)(bp + i * 4);
            Bs1[b1row][b1col + i * 4 + 0] = f2tf32(v.x);
            Bs1[b1row][b1col + i * 4 + 1] = f2tf32(v.y);
            Bs1[b1row][b1col + i * 4 + 2] = f2tf32(v.z);
            Bs1[b1row][b1col + i * 4 + 3] = f2tf32(v.w);
        }
        __syncthreads();
        #pragma unroll
        for (int kk = 0; kk < 32; kk += 8) {
            uint32_t af[4], bf[2][2];
            int r = wm * 16 + grp;
            af[0] = As[r][kk + qk];     af[1] = As[r + 8][kk + qk];
            af[2] = As[r][kk + qk + 4]; af[3] = As[r + 8][kk + qk + 4];
            #pragma unroll
            for (int nt = 0; nt < 2; nt++) {
                bf[nt][0] = Bs1[kk + qk][wn * 16 + nt * 8 + grp];
                bf[nt][1] = Bs1[kk + qk + 4][wn * 16 + nt * 8 + grp];
            }
            #pragma unroll
            for (int nt = 0; nt < 2; nt++) mma_tf32(acc1[nt], af, bf[nt]);
        }
        __syncthreads();
    }

    // stage-1 epilogue: gelu -> St1 (tf32)
    {
        int r = wm * 16 + grp;
        #pragma unroll
        for (int nt = 0; nt < 2; nt++) {
            int c = wn * 16 + nt * 8 + 2 * qk;
            float bb0 = b1[c], bb1 = b1[c + 1];
            St1[r][c]         = f2tf32(gelu_exact(acc1[nt][0] + bb0));
            St1[r][c + 1]     = f2tf32(gelu_exact(acc1[nt][1] + bb1));
            St1[r + 8][c]     = f2tf32(gelu_exact(acc1[nt][2] + bb0));
            St1[r + 8][c + 1] = f2tf32(gelu_exact(acc1[nt][3] + bb1));
        }
    }
    __syncthreads();

    // ---- stage 2: t = gelu(t1) @ w2 (32x128, K=32). Warp tile 16x64 ----
    float acc2[8][4];
    #pragma unroll
    for (int nt = 0; nt < 8; nt++)
        #pragma unroll
        for (int i = 0; i < 4; i++) acc2[nt][i] = 0.f;

    #pragma unroll
    for (int kk = 0; kk < 32; kk += 8) {
        uint32_t af[4];
        int r = wm * 16 + grp;
        af[0] = St1[r][kk + qk];     af[1] = St1[r + 8][kk + qk];
        af[2] = St1[r][kk + qk + 4]; af[3] = St1[r + 8][kk + qk + 4];
        #pragma unroll
        for (int nt = 0; nt < 8; nt++) {
            uint32_t bf[2];
            bf[0] = Bs2[kk + qk][wn * 64 + nt * 8 + grp];
            bf[1] = Bs2[kk + qk + 4][wn * 64 + nt * 8 + grp];
            mma_tf32(acc2[nt], af, bf);
        }
    }

    int n = m0 >> 12;
    int r = wm * 16 + grp;
    #pragma unroll
    for (int nt = 0; nt < 8; nt++) {
        int c = wn * 64 + nt * 8 + 2 * qk;
        float bb0 = b2[c], bb1 = b2[c + 1];
        float v0 = acc2[nt][0] + bb0, v1 = acc2[nt][1] + bb1;
        float v2 = acc2[nt][2] + bb0, v3 = acc2[nt][3] + bb1;
        size_t ro = (size_t)(m0 + r) * CDIM;
        tout[ro + c] = v0;             tout[ro + c + 1] = v1;
        tout[ro + 8 * CDIM + c] = v2;  tout[ro + 8 * CDIM + c + 1] = v3;
        float s0 = v0 + v2, s1 = v1 + v3;
        #pragma unroll
        for (int o = 4; o < 32; o <<= 1) {
            s0 += __shfl_xor_sync(0xffffffffu, s0, o);
            s1 += __shfl_xor_sync(0xffffffffu, s1, o);
        }
        if (lane < 4) {
            atomicAdd(&gsum[n * CDIM + c], s0);
            atomicAdd(&gsum[n * CDIM + c + 1], s1);
        }
    }
}

// ---------------------------------------------------------------------------
// Neighborhood attention — tensor-core tf32; sparse softmax (R12 version).
// ---------------------------------------------------------------------------
#define NA_P_OFF   0
#define NA_Q_OFF   52224
#define NA_K_OFF   61440
#define NA_V_OFF   52224
#define NA_RPB_OFF 87552
#define NA_INV_OFF 88228
#define NA_SMEM    88512

__global__ __launch_bounds__(256)
void k_na(const float* __restrict__ qkv, const float* __restrict__ rpb,
          float* __restrict__ na)
{
    extern __shared__ char smem[];
    uint32_t (*P)[204]  = (uint32_t(*)[204])(smem + NA_P_OFF);
    uint32_t (*Qs)[36]  = (uint32_t(*)[36])(smem + NA_Q_OFF);
    uint32_t (*Ks)[204] = (uint32_t(*)[204])(smem + NA_K_OFF);
    uint32_t (*Vs)[40]  = (uint32_t(*)[40])(smem + NA_V_OFF);
    float* srpb = (float*)(smem + NA_RPB_OFF);
    float* sinv = (float*)(smem + NA_INV_OFF);

    int tid  = threadIdx.x;
    int lane = tid & 31;
    int warp = tid >> 5;
    int grp = lane >> 2, qk = lane & 3;

    int n = blockIdx.y >> 2;
    int h = blockIdx.y & 3;
    int i0 = (blockIdx.x >> 3) * 8, j0 = (blockIdx.x & 7) * 8;
    int wi0 = i0 - 3; wi0 = wi0 < 0 ? 0 : wi0;
    int wj0 = j0 - 3; wj0 = wj0 < 0 ? 0 : wj0;

    if (tid < 169) srpb[tid] = rpb[h * 169 + tid];

    const float* qb = qkv + (size_t)(n * HWP) * 384 + h * DH;

    #pragma unroll
    for (int idx = tid; idx < 64 * 32; idx += 256) {
        int p = idx >> 5, c = idx & 31;
        int i = i0 + (p >> 3), j = j0 + (p & 7);
        Qs[p][c] = f2tf32(qb[(size_t)(i * 64 + j) * 384 + c] * 0.17677669529663687f);
    }
    for (int idx = tid; idx < 8 * 200; idx += 256) {
        int chunk = idx / 200;
        int widx  = idx - chunk * 200;
        int c0 = chunk * 4;
        int rw = (widx * 2341) >> 15; rw = rw > 13 ? 13 : rw;
        int cw = widx - rw * 14;
        int gi = wi0 + rw; gi = gi > 63 ? 63 : gi;
        int gj = wj0 + cw; gj = gj > 63 ? 63 : gj;
        float4 v = *(const float4*)(qb + (size_t)(gi * 64 + gj) * 384 + 128 + c0);
        Ks[c0 + 0][widx] = f2tf32(v.x);
        Ks[c0 + 1][widx] = f2tf32(v.y);
        Ks[c0 + 2][widx] = f2tf32(v.z);
        Ks[c0 + 3][widx] = f2tf32(v.w);
    }
    __syncthreads();

    int mt = warp >> 1;
    int nh = warp & 1;
    int gt0 = nh ? 12 : 0;
    int ngt = nh ? 13 : 12;

    float sacc[13][4];
    #pragma unroll
    for (int t = 0; t < 13; t++)
        #pragma unroll
        for (int i = 0; i < 4; i++) sacc[t][i] = 0.f;

    #pragma unroll
    for (int kk = 0; kk < 32; kk += 8) {
        uint32_t af[4];
        int r = mt * 16 + grp;
        af[0] = Qs[r][kk + qk];     af[1] = Qs[r + 8][kk + qk];
        af[2] = Qs[r][kk + qk + 4]; af[3] = Qs[r + 8][kk + qk + 4];
        #pragma unroll
        for (int t = 0; t < 13; t++) {
            if (t < ngt) {
                int gt = gt0 + t;
                uint32_t bf[2];
                bf[0] = Ks[kk + qk][gt * 8 + grp];
                bf[1] = Ks[kk + qk + 4][gt * 8 + grp];
                mma_tf32(sacc[t], af, bf);
            }
        }
    }

    // ---- scatter: valid -> score+rpb; invalid -> 0.0f (already "exp'd") ----
    {
        int r0 = mt * 16 + grp, r1 = r0 + 8;
        int i_a = i0 + (r0 >> 3), j_a = j0 + (r0 & 7);
        int ni_a = i_a - 3; ni_a = ni_a < 0 ? 0 : (ni_a > 57 ? 57 : ni_a);
        int nj_a = j_a - 3; nj_a = nj_a < 0 ? 0 : (nj_a > 57 ? 57 : nj_a);
        int di_a = ni_a - wi0, dj_a = nj_a - wj0;
        int rb_a = (ni_a - i_a + 6) * 13 + (nj_a - j_a + 6);
        int i_b = i0 + (r1 >> 3), j_b = j0 + (r1 & 7);
        int ni_b = i_b - 3; ni_b = ni_b < 0 ? 0 : (ni_b > 57 ? 57 : ni_b);
        int nj_b = j_b - 3; nj_b = nj_b < 0 ? 0 : (nj_b > 57 ? 57 : nj_b);
        int di_b = ni_b - wi0, dj_b = nj_b - wj0;
        int rb_b = (ni_b - i_b + 6) * 13 + (nj_b - j_b + 6);

        #pragma unroll
        for (int t = 0; t < 13; t++) {
            if (t >= ngt) break;
            int gt = gt0 + t;
            #pragma unroll
            for (int cc = 0; cc < 2; cc++) {
                int col = gt * 8 + 2 * qk + cc;
                int rw = (col * 2341) >> 15;
                int cw = col - rw * 14;
                int a0 = rw - di_a, b0 = cw - dj_a;
                uint32_t v0 = ((unsigned)a0 < 7u && (unsigned)b0 < 7u)
                         ? __float_as_uint(sacc[t][cc] + srpb[rb_a + a0 * 13 + b0]) : 0u;
                P[r0][col] = v0;
                int a1 = rw - di_b, b1 = cw - dj_b;
                uint32_t v1 = ((unsigned)a1 < 7u && (unsigned)b1 < 7u)
                         ? __float_as_uint(sacc[t][2 + cc] + srpb[rb_b + a1 * 13 + b1]) : 0u;
                P[r1][col] = v1;
            }
        }
    }
    __syncthreads();

    #pragma unroll
    for (int idx = tid; idx < 200 * 32; idx += 256) {
        int widx = idx >> 5, c = idx & 31;
        int rw = (widx * 2341) >> 15; rw = rw > 13 ? 13 : rw;
        int cw = widx - rw * 14;
        int gi = wi0 + rw; gi = gi > 63 ? 63 : gi;
        int gj = wj0 + cw; gj = gj > 63 ? 63 : gj;
        Vs[widx][c] = f2tf32(qb[(size_t)(gi * 64 + gj) * 384 + 256 + c]);
    }

    // ---- sparse softmax: only the 49 valid entries per pixel ----
    {
        int p0w = warp * 8;
        #pragma unroll
        for (int pp = 0; pp < 8; pp++) {
            int p = p0w + pp;
            int i = i0 + (p >> 3), j = j0 + (p & 7);
            int ni = i - 3; ni = ni < 0 ? 0 : (ni > 57 ? 57 : ni);
            int nj = j - 3; nj = nj < 0 ? 0 : (nj > 57 ? 57 : nj);
            int wbase = (ni - wi0) * 14 + (nj - wj0);

            int a0 = (lane * 9363) >> 16, b0 = lane - a0 * 7;
            int col0 = wbase + a0 * 14 + b0;
            float v0 = __uint_as_float(P[p][col0]);
            int e1 = lane + 32;
            int a1 = (e1 * 9363) >> 16, b1 = e1 - a1 * 7;
            int col1 = wbase + a1 * 14 + b1;
            bool has1 = lane < 17;
            float v1 = has1 ? __uint_as_float(P[p][col1]) : -1e30f;

            float m = fmaxf(v0, v1);
            #pragma unroll
            for (int o = 16; o > 0; o >>= 1) m = fmaxf(m, __shfl_xor_sync(0xffffffffu, m, o));
            float ex0 = __expf(v0 - m);
            float ex1 = has1 ? __expf(v1 - m) : 0.f;
            float s = ex0 + ex1;
            #pragma unroll
            for (int o = 16; o > 0; o >>= 1) s += __shfl_xor_sync(0xffffffffu, s, o);
            P[p][col0] = f2tf32(ex0);
            if (has1) P[p][col1] = f2tf32(ex1);
            if (lane == 0) sinv[p] = 1.0f / s;
        }
    }
    __syncthreads();

    float oacc[2][4];
    #pragma unroll
    for (int nt = 0; nt < 2; nt++)
        #pragma unroll
        for (int i = 0; i < 4; i++) oacc[nt][i] = 0.f;

    int c0 = nh * 16;
    for (int kt = 0; kt < 200; kt += 8) {
        uint32_t af[4];
        int r = mt * 16 + grp;
        af[0] = P[r][kt + qk];     af[1] = P[r + 8][kt + qk];
        af[2] = P[r][kt + qk + 4]; af[3] = P[r + 8][kt + qk + 4];
        #pragma unroll
        for (int nt = 0; nt < 2; nt++) {
            uint32_t bf[2];
            bf[0] = Vs[kt + qk][c0 + nt * 8 + grp];
            bf[1] = Vs[kt + qk + 4][c0 + nt * 8 + grp];
            mma_tf32(oacc[nt], af, bf);
        }
    }

    {
        int r0 = mt * 16 + grp, r1 = r0 + 8;
        float inv0 = sinv[r0], inv1 = sinv[r1];
        int ia = i0 + (r0 >> 3), ja = j0 + (r0 & 7);
        int ib = i0 + (r1 >> 3), jb = j0 + (r1 & 7);
        size_t oa = (size_t)(n * HWP + ia * 64 + ja) * CDIM + h * DH;
        size_t ob = (size_t)(n * HWP + ib * 64 + jb) * CDIM + h * DH;
        #pragma unroll
        for (int nt = 0; nt < 2; nt++) {
            int cc0 = c0 + nt * 8 + 2 * qk;
            na[oa + cc0]     = oacc[nt][0] * inv0;
            na[oa + cc0 + 1] = oacc[nt][1] * inv0;
            na[ob + cc0]     = oacc[nt][2] * inv1;
            na[ob + cc0 + 1] = oacc[nt][3] * inv1;
        }
    }
}

// ---------------------------------------------------------------------------
// Fused proj GEMM (bf16) + gate + residual + LN2.  BM=32, grid 512,
// 128 threads (warp tile 16x64) — was BM=64/grid 256 (occ 10.9%).
// ---------------------------------------------------------------------------
__global__ __launch_bounds__(128)
void k_proj_ln(const float* __restrict__ A /*na*/, const float* __restrict__ B /*proj_w*/,
               const float* __restrict__ bias,
               const float* __restrict__ xs, const float* __restrict__ t,
               const float* __restrict__ gsum,
               const float* __restrict__ ca1w, const float* __restrict__ ca1b,
               const float* __restrict__ ca2w, const float* __restrict__ ca2b,
               const float* __restrict__ w2, const float* __restrict__ b2,
               float* __restrict__ x2, float* __restrict__ xn2)
{
    __shared__ union SU {
        struct { uint32_t Asp[32][20]; uint32_t Bsp[16][136]; } gm;
        float x2s[32][132];
    } sm;
    __shared__ float sgm[CDIM];
    __shared__ float sr7[7];
    __shared__ float sgarr[CDIM];

    int tid  = threadIdx.x;
    int lane = tid & 31;
    int warp = tid >> 5;
    int grp = lane >> 2, qk = lane & 3;
    int wm = warp & 1, wn = warp >> 1;
    int m0 = blockIdx.x * 32;
    int n = m0 >> 12;

    float acc[8][4];
    #pragma unroll
    for (int nt = 0; nt < 8; nt++)
        #pragma unroll
        for (int i = 0; i < 4; i++) acc[nt][i] = 0.f;

    int arow = tid >> 2, kseg = (tid & 3) * 8, apair = (tid & 3) * 4;
    int pr = tid >> 3, bc = (tid & 7) * 16;

    for (int k0 = 0; k0 < 128; k0 += 32) {
        const float* ap = A + (size_t)(m0 + arow) * CDIM + k0 + kseg;
        float4 a0 = *(const float4*)ap, a1 = *(const float4*)(ap + 4);
        sm.gm.Asp[arow][apair + 0] = pack_bf16(a0.x, a0.y);
        sm.gm.Asp[arow][apair + 1] = pack_bf16(a0.z, a0.w);
        sm.gm.Asp[arow][apair + 2] = pack_bf16(a1.x, a1.y);
        sm.gm.Asp[arow][apair + 3] = pack_bf16(a1.z, a1.w);

        const float* bp = B + (size_t)(k0 + 2 * pr) * CDIM + bc;
        #pragma unroll
        for (int i = 0; i < 4; i++) {
            float4 ev = *(const float4*)(bp + i * 4);
            float4 ov = *(const float4*)(bp + CDIM + i * 4);
            sm.gm.Bsp[pr][bc + i * 4 + 0] = pack_bf16(ev.x, ov.x);
            sm.gm.Bsp[pr][bc + i * 4 + 1] = pack_bf16(ev.y, ov.y);
            sm.gm.Bsp[pr][bc + i * 4 + 2] = pack_bf16(ev.z, ov.z);
            sm.gm.Bsp[pr][bc + i * 4 + 3] = pack_bf16(ev.w, ov.w);
        }
        __syncthreads();
        #pragma unroll
        for (int ks = 0; ks < 2; ks++) {
            int pb8 = ks * 8;
            uint32_t af[4];
            int r = wm * 16 + grp;
            af[0] = sm.gm.Asp[r][pb8 + qk];     af[1] = sm.gm.Asp[r + 8][pb8 + qk];
            af[2] = sm.gm.Asp[r][pb8 + qk + 4]; af[3] = sm.gm.Asp[r + 8][pb8 + qk + 4];
            #pragma unroll
            for (int nt = 0; nt < 8; nt++) {
                uint32_t bf[2];
                bf[0] = sm.gm.Bsp[pb8 + qk][wn * 64 + nt * 8 + grp];
                bf[1] = sm.gm.Bsp[pb8 + qk + 4][wn * 64 + nt * 8 + grp];
                mma_bf16_k16(acc[nt], af, bf);
            }
        }
        __syncthreads();
    }

    // ---- channel-attention gate in-block ----
    sgm[tid] = gsum[n * CDIM + tid] * (1.0f / HWP);
    __syncthreads();
    if (warp == 0) {
        float part[7];
        #pragma unroll
        for (int j = 0; j < 7; j++) part[j] = 0.f;
        #pragma unroll
        for (int k = 0; k < 4; k++) {
            int c = lane + 32 * k;
            float gv = sgm[c];
            #pragma unroll
            for (int j = 0; j < 7; j++) part[j] += gv * ca1w[c * 7 + j];
        }
        #pragma unroll
        for (int j = 0; j < 7; j++) {
            #pragma unroll
            for (int o = 16; o > 0; o >>= 1)
                part[j] += __shfl_xor_sync(0xffffffffu, part[j], o);
        }
        if (lane == 0) {
            #pragma unroll
            for (int j = 0; j < 7; j++) sr7[j] = fmaxf(part[j] + ca1b[j], 0.f);
        }
    }
    __syncthreads();
    {
        float s = ca2b[tid];
        #pragma unroll
        for (int j = 0; j < 7; j++) s += sr7[j] * ca2w[j * CDIM + tid];
        sgarr[tid] = (1.0f / (1.0f + expf(-s))) * 0.02f;
    }
    __syncthreads();

    // epilogue: x2 value -> smem
    {
        int r = wm * 16 + grp;
        size_t ro0 = (size_t)(m0 + r) * CDIM;
        size_t ro1 = (size_t)(m0 + r + 8) * CDIM;
        #pragma unroll
        for (int nt = 0; nt < 8; nt++) {
            int c = wn * 64 + nt * 8 + 2 * qk;
            float bb0 = bias[c], bb1 = bias[c + 1];
            float g0 = sgarr[c], g1 = sgarr[c + 1];
            sm.x2s[r][c]         = acc[nt][0] + bb0 + xs[ro0 + c]     + t[ro0 + c]     * g0;
            sm.x2s[r][c + 1]     = acc[nt][1] + bb1 + xs[ro0 + c + 1] + t[ro0 + c + 1] * g1;
            sm.x2s[r + 8][c]     = acc[nt][2] + bb0 + xs[ro1 + c]     + t[ro1 + c]     * g0;
            sm.x2s[r + 8][c + 1] = acc[nt][3] + bb1 + xs[ro1 + c + 1] + t[ro1 + c + 1] * g1;
        }
    }
    __syncthreads();

    float w2r[4], b2r[4];
    #pragma unroll
    for (int k = 0; k < 4; k++) { w2r[k] = w2[lane + 32 * k]; b2r[k] = b2[lane + 32 * k]; }

    #pragma unroll
    for (int rr = 0; rr < 8; rr++) {
        int r = warp * 8 + rr;
        float v[4];
        float sum = 0.f, sq = 0.f;
        #pragma unroll
        for (int k = 0; k < 4; k++) {
            v[k] = sm.x2s[r][lane + 32 * k];
            sum += v[k]; sq += v[k] * v[k];
        }
        #pragma unroll
        for (int o = 16; o > 0; o >>= 1) {
            sum += __shfl_xor_sync(0xffffffffu, sum, o);
            sq  += __shfl_xor_sync(0xffffffffu, sq, o);
        }
        float mu = sum * (1.0f / CDIM);
        float rs = rsqrtf(sq * (1.0f / CDIM) - mu * mu + 1e-5f);
        size_t ro = (size_t)(m0 + r) * CDIM;
        #pragma unroll
        for (int k = 0; k < 4; k++) {
            x2[ro + lane + 32 * k]  = v[k];
            xn2[ro + lane + 32 * k] = (v[k] - mu) * rs * w2r[k] + b2r[k];
        }
    }
}

// ---------------------------------------------------------------------------
// Launch
// ---------------------------------------------------------------------------
extern "C" void kernel_launch(void* const* d_in, const int* in_sizes, int n_in,
                              void* d_out, int out_size)
{
    const float* x      = (const float*)d_in[0];
    const float* ln1_w  = (const float*)d_in[1];
    const float* ln1_b  = (const float*)d_in[2];
    const float* ln2_w  = (const float*)d_in[3];
    const float* ln2_b  = (const float*)d_in[4];
    const float* qkv_w  = (const float*)d_in[5];
    const float* qkv_b  = (const float*)d_in[6];
    const float* proj_w = (const float*)d_in[7];
    const float* proj_b = (const float*)d_in[8];
    const float* rpb    = (const float*)d_in[9];
    const float* conv1_w= (const float*)d_in[10];
    const float* conv1_b= (const float*)d_in[11];
    const float* conv2_w= (const float*)d_in[12];
    const float* conv2_b= (const float*)d_in[13];
    const float* ca1_w  = (const float*)d_in[14];
    const float* ca1_b  = (const float*)d_in[15];
    const float* ca2_w  = (const float*)d_in[16];
    const float* ca2_b  = (const float*)d_in[17];
    const float* fc1_w  = (const float*)d_in[18];
    const float* fc1_b  = (const float*)d_in[19];
    const float* fc2_w  = (const float*)d_in[20];
    const float* fc2_b  = (const float*)d_in[21];
    float* out = (float*)d_out;

    float* scr = nullptr;
    cudaGetSymbolAddress((void**)&scr, d_scratch);
    float* xs   = scr + OFF_XS;
    float* xn   = scr + OFF_XN;
    float* qkv  = scr + OFF_QKV;
    float* t    = scr + OFF_T;
    float* na   = scr + OFF_NA;
    float* x2   = scr + OFF_X2;
    float* xn2  = scr + OFF_XN2;
    float* h1   = scr + OFF_H1;
    float* gsum = scr + OFF_GSUM;

    cudaFuncSetAttribute(k_na, cudaFuncAttributeMaxDynamicSharedMemorySize, NA_SMEM);

    // 1. transpose + LN1 (+ zero gsum)
    k_transpose_ln<<<ROWS / 32, 128>>>(x, ln1_w, ln1_b, xs, xn, gsum);
    // 2. qkv GEMM (bf16): 16384 x 384 x 128
    k_mma_bf16<EPI_NONE><<<dim3(6, ROWS / 64), 128>>>(xn, qkv_w, qkv_b, qkv,
                                                      ROWS, 384, 128, nullptr);
    // 3. fused conv1+gelu+conv2+colsum (BM=32, grid 512)
    k_conv<<<ROWS / 32, 128>>>(xn, conv1_w, conv1_b, conv2_w, conv2_b, t, gsum);
    // 4. neighborhood attention (tensor-core tf32, sparse softmax)
    k_na<<<dim3(64, NB * NHEAD), 256, NA_SMEM>>>(qkv, rpb, na);
    // 5. fused proj (bf16) + gate + residual + LN2 (BM=32, grid 512)
    k_proj_ln<<<ROWS / 32, 128>>>(na, proj_w, proj_b, xs, t, gsum,
                                  ca1_w, ca1_b, ca2_w, ca2_b,
                                  ln2_w, ln2_b, x2, xn2);
    // 6. fc1 + gelu (bf16): 16384 x 512 x 128
    k_mma_bf16<EPI_GELU><<<dim3(8, ROWS / 64), 128>>>(xn2, fc1_w, fc1_b, h1,
                                                      ROWS, 512, 128, nullptr);
    // 7. fc2 + residual (bf16), write NCHW output
    k_mma_bf16<EPI_OUT><<<dim3(2, ROWS / 64), 128>>>(h1, fc2_w, fc2_b, out,
                                                     ROWS, 128, 512, x2);
}

// round 14
// speedup vs baseline: 1.0269x; 1.0269x over previous
#include <cuda_runtime.h>
#include <cuda_bf16.h>
#include <math.h>
#include <stdint.h>

// ---------------------------------------------------------------------------
// Problem constants
// ---------------------------------------------------------------------------
#define NB    4
#define CDIM  128
#define HWP   4096           // 64*64
#define ROWS  (NB * HWP)     // 16384
#define NHEAD 4
#define DH    32
#define KS    7

// Scratch arena layout (floats)
#define OFF_XS    0u
#define OFF_XN    2097152u            // 16384*128
#define OFF_QKV   4194304u            // len 16384*384
#define OFF_T     11010048u           // len 16384*128
#define OFF_NA    13107200u
#define OFF_X2    15204352u
#define OFF_XN2   17301504u
#define OFF_H1    19398656u           // len 16384*512
#define OFF_GSUM  27787264u           // 512
#define SCRATCH_FLOATS 27788288u

__device__ float d_scratch[SCRATCH_FLOATS];

__device__ __forceinline__ float gelu_exact(float x) {
    return 0.5f * x * (1.0f + erff(x * 0.7071067811865476f));
}

__device__ __forceinline__ uint32_t f2tf32(float f) {
    uint32_t r;
    asm("cvt.rna.tf32.f32 %0, %1;" : "=r"(r) : "f"(f));
    return r;
}

__device__ __forceinline__ void mma_tf32(float d[4], const uint32_t a[4], const uint32_t b[2]) {
    asm volatile(
        "mma.sync.aligned.m16n8k8.row.col.f32.tf32.tf32.f32 "
        "{%0,%1,%2,%3},{%4,%5,%6,%7},{%8,%9},{%0,%1,%2,%3};\n"
        : "+f"(d[0]), "+f"(d[1]), "+f"(d[2]), "+f"(d[3])
        : "r"(a[0]), "r"(a[1]), "r"(a[2]), "r"(a[3]), "r"(b[0]), "r"(b[1]));
}

__device__ __forceinline__ void mma_bf16_k16(float d[4], const uint32_t a[4], const uint32_t b[2]) {
    asm volatile(
        "mma.sync.aligned.m16n8k16.row.col.f32.bf16.bf16.f32 "
        "{%0,%1,%2,%3},{%4,%5,%6,%7},{%8,%9},{%0,%1,%2,%3};\n"
        : "+f"(d[0]), "+f"(d[1]), "+f"(d[2]), "+f"(d[3])
        : "r"(a[0]), "r"(a[1]), "r"(a[2]), "r"(a[3]), "r"(b[0]), "r"(b[1]));
}

// pack (lo, hi) floats into bf16x2 (lo in lower 16 bits = lower k index)
__device__ __forceinline__ uint32_t pack_bf16(float lo, float hi) {
    uint32_t r;
    asm("cvt.rn.bf16x2.f32 %0, %1, %2;" : "=r"(r) : "f"(hi), "f"(lo));
    return r;
}

// ---------------------------------------------------------------------------
// Kernel 1: NCHW -> NHWC transpose + LayerNorm1.  32 pixels per block.
// ---------------------------------------------------------------------------
__global__ __launch_bounds__(128)
void k_transpose_ln(const float* __restrict__ x,
                    const float* __restrict__ w, const float* __restrict__ b,
                    float* __restrict__ xs, float* __restrict__ xn,
                    float* __restrict__ gsum)
{
    __shared__ float s[32][129];
    __shared__ float smu[32], srs[32];
    int tid = threadIdx.x;
    if (blockIdx.x == 0) {
        #pragma unroll
        for (int i = 0; i < 4; i++) gsum[tid + i * 128] = 0.f;
    }
    int row0 = blockIdx.x * 32;
    int n  = row0 >> 12;
    int p0 = row0 & 4095;
    int pl = tid & 31;
    int cg = tid >> 5;       // 0..3

    #pragma unroll 4
    for (int it = 0; it < 32; it++) {
        int c = it * 4 + cg;
        s[pl][c] = x[((size_t)(n * CDIM + c) << 12) + p0 + pl];
    }
    __syncthreads();

    if (tid < 32) {
        float sum = 0.f, sq = 0.f;
        #pragma unroll 8
        for (int c = 0; c < CDIM; c++) { float v = s[tid][c]; sum += v; sq += v * v; }
        float mu  = sum * (1.0f / CDIM);
        float var = sq * (1.0f / CDIM) - mu * mu;
        smu[tid] = mu;
        srs[tid] = rsqrtf(var + 1e-5f);
    }
    __syncthreads();

    float wc = w[tid], bc = b[tid];
    #pragma unroll 4
    for (int it = 0; it < 32; it++) {
        float v = s[it][tid];
        size_t o = (size_t)(row0 + it) * CDIM + tid;
        xs[o] = v;
        xn[o] = (v - smu[it]) * srs[it] * wc + bc;
    }
}

// ---------------------------------------------------------------------------
// Epilogue helpers
// ---------------------------------------------------------------------------
#define EPI_NONE 0
#define EPI_GELU 1
#define EPI_OUT  3   // out NCHW = acc+bias + e1(x2)

template<int EPI>
__device__ __forceinline__ void epi_write(float* __restrict__ C, int row, int col,
                                          int N, float v, const float* __restrict__ e1)
{
    if (EPI == EPI_GELU) {
        C[(size_t)row * N + col] = gelu_exact(v);
    } else if (EPI == EPI_NONE) {
        C[(size_t)row * N + col] = v;
    } else { // EPI_OUT: write NCHW
        v += e1[(size_t)row * CDIM + col];
        int bn = row >> 12, p = row & 4095;
        C[((size_t)(bn * CDIM + col) << 12) + p] = v;
    }
}

// ---------------------------------------------------------------------------
// Pipelined bf16 GEMM (m16n8k16): BM=64, BN=64, BK=32, 128 threads.
// ---------------------------------------------------------------------------
template<int EPI>
__global__ __launch_bounds__(128)
void k_mma_bf16(const float* __restrict__ A, const float* __restrict__ B,
                const float* __restrict__ bias, float* __restrict__ C,
                int M, int N, int K, const float* __restrict__ e1)
{
    constexpr int BM = 64, BN = 64, BK = 32;
    __shared__ uint32_t Asp[BM][20];
    __shared__ uint32_t Bsp[BK / 2][72];

    int tid  = threadIdx.x;
    int lane = tid & 31;
    int warp = tid >> 5;
    int wm = warp & 1, wn = warp >> 1;
    int m0 = blockIdx.y * BM, n0 = blockIdx.x * BN;
    int grp = lane >> 2, qk = lane & 3;

    float d[2][4][4];
    #pragma unroll
    for (int mt = 0; mt < 2; mt++)
        #pragma unroll
        for (int nt = 0; nt < 4; nt++)
            #pragma unroll
            for (int i = 0; i < 4; i++) d[mt][nt][i] = 0.f;

    int arow = tid >> 1, kseg = (tid & 1) * 16, apair = (tid & 1) * 8;
    int pr = tid >> 3, bc = (tid & 7) * 8;     // B: pair-row, col base

    float4 pa0, pa1, pa2, pa3, pb0, pb1, pb2, pb3;

#define LDG_TILE(k0) { \
    const float* ap = A + (size_t)(m0 + arow) * K + (k0) + kseg; \
    pa0 = *(const float4*)ap;       pa1 = *(const float4*)(ap + 4); \
    pa2 = *(const float4*)(ap + 8); pa3 = *(const float4*)(ap + 12); \
    const float* bp = B + (size_t)((k0) + 2 * pr) * N + n0 + bc; \
    pb0 = *(const float4*)bp;       pb1 = *(const float4*)(bp + 4); \
    pb2 = *(const float4*)(bp + N); pb3 = *(const float4*)(bp + N + 4); }

#define STS_TILE() { \
    Asp[arow][apair+0]=pack_bf16(pa0.x,pa0.y); Asp[arow][apair+1]=pack_bf16(pa0.z,pa0.w); \
    Asp[arow][apair+2]=pack_bf16(pa1.x,pa1.y); Asp[arow][apair+3]=pack_bf16(pa1.z,pa1.w); \
    Asp[arow][apair+4]=pack_bf16(pa2.x,pa2.y); Asp[arow][apair+5]=pack_bf16(pa2.z,pa2.w); \
    Asp[arow][apair+6]=pack_bf16(pa3.x,pa3.y); Asp[arow][apair+7]=pack_bf16(pa3.z,pa3.w); \
    Bsp[pr][bc+0]=pack_bf16(pb0.x,pb2.x); Bsp[pr][bc+1]=pack_bf16(pb0.y,pb2.y); \
    Bsp[pr][bc+2]=pack_bf16(pb0.z,pb2.z); Bsp[pr][bc+3]=pack_bf16(pb0.w,pb2.w); \
    Bsp[pr][bc+4]=pack_bf16(pb1.x,pb3.x); Bsp[pr][bc+5]=pack_bf16(pb1.y,pb3.y); \
    Bsp[pr][bc+6]=pack_bf16(pb1.z,pb3.z); Bsp[pr][bc+7]=pack_bf16(pb1.w,pb3.w); }

#define MMA_TILE() { \
    _Pragma("unroll") \
    for (int ks = 0; ks < 2; ks++) { \
        int pb8 = ks * 8; \
        uint32_t af[2][4], bf[4][2]; \
        _Pragma("unroll") \
        for (int mt = 0; mt < 2; mt++) { \
            int r = wm * 32 + mt * 16 + grp; \
            af[mt][0] = Asp[r][pb8 + qk];     af[mt][1] = Asp[r + 8][pb8 + qk]; \
            af[mt][2] = Asp[r][pb8 + qk + 4]; af[mt][3] = Asp[r + 8][pb8 + qk + 4]; \
        } \
        _Pragma("unroll") \
        for (int nt = 0; nt < 4; nt++) { \
            int cidx = wn * 32 + nt * 8 + grp; \
            bf[nt][0] = Bsp[pb8 + qk][cidx]; bf[nt][1] = Bsp[pb8 + qk + 4][cidx]; \
        } \
        _Pragma("unroll") \
        for (int mt = 0; mt < 2; mt++) \
            _Pragma("unroll") \
            for (int nt = 0; nt < 4; nt++) \
                mma_bf16_k16(d[mt][nt], af[mt], bf[nt]); \
    } }

    LDG_TILE(0);
    STS_TILE();
    __syncthreads();
    for (int k0 = BK; k0 < K; k0 += BK) {
        LDG_TILE(k0);
        MMA_TILE();
        __syncthreads();
        STS_TILE();
        __syncthreads();
    }
    MMA_TILE();

#undef LDG_TILE
#undef STS_TILE
#undef MMA_TILE

    #pragma unroll
    for (int mt = 0; mt < 2; mt++) {
        int rbase = m0 + wm * 32 + mt * 16 + grp;
        #pragma unroll
        for (int nt = 0; nt < 4; nt++) {
            int cbase = n0 + wn * 32 + nt * 8 + 2 * qk;
            float b0 = bias[cbase], b1 = bias[cbase + 1];
            epi_write<EPI>(C, rbase,     cbase,     N, d[mt][nt][0] + b0, e1);
            epi_write<EPI>(C, rbase,     cbase + 1, N, d[mt][nt][1] + b1, e1);
            epi_write<EPI>(C, rbase + 8, cbase,     N, d[mt][nt][2] + b0, e1);
            epi_write<EPI>(C, rbase + 8, cbase + 1, N, d[mt][nt][3] + b1, e1);
        }
    }
}

// ---------------------------------------------------------------------------
// Fused conv1 + GELU + conv2 + spatial-mean.  64 rows per block, 128 threads.
// ---------------------------------------------------------------------------
__global__ __launch_bounds__(128)
void k_conv(const float* __restrict__ xn,
            const float* __restrict__ w1, const float* __restrict__ b1,
            const float* __restrict__ w2, const float* __restrict__ b2,
            float* __restrict__ tout, float* __restrict__ gsum)
{
    __shared__ uint32_t As[64][36];
    __shared__ uint32_t Bs1[32][40];
    __shared__ uint32_t St1[64][36];
    __shared__ uint32_t Bs2[32][136];

    int tid  = threadIdx.x;
    int lane = tid & 31;
    int warp = tid >> 5;
    int grp = lane >> 2, qk = lane & 3;
    int m0 = blockIdx.x * 64;

    {
        int r = tid >> 2, c0 = (tid & 3) * 32;
        #pragma unroll
        for (int i = 0; i < 8; i++) {
            float4 v = *(const float4*)(w2 + (size_t)r * 128 + c0 + i * 4);
            Bs2[r][c0 + i * 4 + 0] = f2tf32(v.x);
            Bs2[r][c0 + i * 4 + 1] = f2tf32(v.y);
            Bs2[r][c0 + i * 4 + 2] = f2tf32(v.z);
            Bs2[r][c0 + i * 4 + 3] = f2tf32(v.w);
        }
    }

    float acc1[4][4];
    #pragma unroll
    for (int nt = 0; nt < 4; nt++)
        #pragma unroll
        for (int i = 0; i < 4; i++) acc1[nt][i] = 0.f;

    int arow = tid >> 1, kseg = (tid & 1) * 16;
    int b1row = tid >> 2, b1col = (tid & 3) * 8;

    for (int k0 = 0; k0 < 128; k0 += 32) {
        const float* ap = xn + (size_t)(m0 + arow) * CDIM + k0 + kseg;
        #pragma unroll
        for (int i = 0; i < 4; i++) {
            float4 v = *(const float4*)(ap + i * 4);
            As[arow][kseg + i * 4 + 0] = f2tf32(v.x);
            As[arow][kseg + i * 4 + 1] = f2tf32(v.y);
            As[arow][kseg + i * 4 + 2] = f2tf32(v.z);
            As[arow][kseg + i * 4 + 3] = f2tf32(v.w);
        }
        const float* bp = w1 + (size_t)(k0 + b1row) * 32 + b1col;
        #pragma unroll
        for (int i = 0; i < 2; i++) {
            float4 v = *(const float4*)(bp + i * 4);
            Bs1[b1row][b1col + i * 4 + 0] = f2tf32(v.x);
            Bs1[b1row][b1col + i * 4 + 1] = f2tf32(v.y);
            Bs1[b1row][b1col + i * 4 + 2] = f2tf32(v.z);
            Bs1[b1row][b1col + i * 4 + 3] = f2tf32(v.w);
        }
        __syncthreads();
        #pragma unroll
        for (int kk = 0; kk < 32; kk += 8) {
            uint32_t af[4], bf[4][2];
            int r = warp * 16 + grp;
            af[0] = As[r][kk + qk];     af[1] = As[r + 8][kk + qk];
            af[2] = As[r][kk + qk + 4]; af[3] = As[r + 8][kk + qk + 4];
            #pragma unroll
            for (int nt = 0; nt < 4; nt++) {
                bf[nt][0] = Bs1[kk + qk][nt * 8 + grp];
                bf[nt][1] = Bs1[kk + qk + 4][nt * 8 + grp];
            }
            #pragma unroll
            for (int nt = 0; nt < 4; nt++) mma_tf32(acc1[nt], af, bf[nt]);
        }
        __syncthreads();
    }

    {
        int r = warp * 16 + grp;
        #pragma unroll
        for (int nt = 0; nt < 4; nt++) {
            int c = nt * 8 + 2 * qk;
            float bb0 = b1[c], bb1 = b1[c + 1];
            St1[r][c]         = f2tf32(gelu_exact(acc1[nt][0] + bb0));
            St1[r][c + 1]     = f2tf32(gelu_exact(acc1[nt][1] + bb1));
            St1[r + 8][c]     = f2tf32(gelu_exact(acc1[nt][2] + bb0));
            St1[r + 8][c + 1] = f2tf32(gelu_exact(acc1[nt][3] + bb1));
        }
    }
    __syncthreads();

    float acc2[16][4];
    #pragma unroll
    for (int nt = 0; nt < 16; nt++)
        #pragma unroll
        for (int i = 0; i < 4; i++) acc2[nt][i] = 0.f;

    #pragma unroll
    for (int kk = 0; kk < 32; kk += 8) {
        uint32_t af[4];
        int r = warp * 16 + grp;
        af[0] = St1[r][kk + qk];     af[1] = St1[r + 8][kk + qk];
        af[2] = St1[r][kk + qk + 4]; af[3] = St1[r + 8][kk + qk + 4];
        #pragma unroll
        for (int nt = 0; nt < 16; nt++) {
            uint32_t bf[2];
            bf[0] = Bs2[kk + qk][nt * 8 + grp];
            bf[1] = Bs2[kk + qk + 4][nt * 8 + grp];
            mma_tf32(acc2[nt], af, bf);
        }
    }

    int n = m0 >> 12;
    int r = warp * 16 + grp;
    #pragma unroll
    for (int nt = 0; nt < 16; nt++) {
        int c = nt * 8 + 2 * qk;
        float bb0 = b2[c], bb1 = b2[c + 1];
        float v0 = acc2[nt][0] + bb0, v1 = acc2[nt][1] + bb1;
        float v2 = acc2[nt][2] + bb0, v3 = acc2[nt][3] + bb1;
        size_t ro = (size_t)(m0 + r) * CDIM;
        tout[ro + c] = v0;             tout[ro + c + 1] = v1;
        tout[ro + 8 * CDIM + c] = v2;  tout[ro + 8 * CDIM + c + 1] = v3;
        float s0 = v0 + v2, s1 = v1 + v3;
        #pragma unroll
        for (int o = 4; o < 32; o <<= 1) {
            s0 += __shfl_xor_sync(0xffffffffu, s0, o);
            s1 += __shfl_xor_sync(0xffffffffu, s1, o);
        }
        if (lane < 4) {
            atomicAdd(&gsum[n * CDIM + c], s0);
            atomicAdd(&gsum[n * CDIM + c + 1], s1);
        }
    }
}

// ---------------------------------------------------------------------------
// Neighborhood attention — tensor-core tf32; sparse softmax.
// ---------------------------------------------------------------------------
#define NA_P_OFF   0
#define NA_Q_OFF   52224
#define NA_K_OFF   61440
#define NA_V_OFF   52224
#define NA_RPB_OFF 87552
#define NA_INV_OFF 88228
#define NA_SMEM    88512

__global__ __launch_bounds__(256)
void k_na(const float* __restrict__ qkv, const float* __restrict__ rpb,
          float* __restrict__ na)
{
    extern __shared__ char smem[];
    uint32_t (*P)[204]  = (uint32_t(*)[204])(smem + NA_P_OFF);
    uint32_t (*Qs)[36]  = (uint32_t(*)[36])(smem + NA_Q_OFF);
    uint32_t (*Ks)[204] = (uint32_t(*)[204])(smem + NA_K_OFF);
    uint32_t (*Vs)[40]  = (uint32_t(*)[40])(smem + NA_V_OFF);
    float* srpb = (float*)(smem + NA_RPB_OFF);
    float* sinv = (float*)(smem + NA_INV_OFF);

    int tid  = threadIdx.x;
    int lane = tid & 31;
    int warp = tid >> 5;
    int grp = lane >> 2, qk = lane & 3;

    int n = blockIdx.y >> 2;
    int h = blockIdx.y & 3;
    int i0 = (blockIdx.x >> 3) * 8, j0 = (blockIdx.x & 7) * 8;
    int wi0 = i0 - 3; wi0 = wi0 < 0 ? 0 : wi0;
    int wj0 = j0 - 3; wj0 = wj0 < 0 ? 0 : wj0;

    if (tid < 169) srpb[tid] = rpb[h * 169 + tid];

    const float* qb = qkv + (size_t)(n * HWP) * 384 + h * DH;

    #pragma unroll
    for (int idx = tid; idx < 64 * 32; idx += 256) {
        int p = idx >> 5, c = idx & 31;
        int i = i0 + (p >> 3), j = j0 + (p & 7);
        Qs[p][c] = f2tf32(qb[(size_t)(i * 64 + j) * 384 + c] * 0.17677669529663687f);
    }
    for (int idx = tid; idx < 8 * 200; idx += 256) {
        int chunk = idx / 200;
        int widx  = idx - chunk * 200;
        int c0 = chunk * 4;
        int rw = (widx * 2341) >> 15; rw = rw > 13 ? 13 : rw;
        int cw = widx - rw * 14;
        int gi = wi0 + rw; gi = gi > 63 ? 63 : gi;
        int gj = wj0 + cw; gj = gj > 63 ? 63 : gj;
        float4 v = *(const float4*)(qb + (size_t)(gi * 64 + gj) * 384 + 128 + c0);
        Ks[c0 + 0][widx] = f2tf32(v.x);
        Ks[c0 + 1][widx] = f2tf32(v.y);
        Ks[c0 + 2][widx] = f2tf32(v.z);
        Ks[c0 + 3][widx] = f2tf32(v.w);
    }
    __syncthreads();

    int mt = warp >> 1;
    int nh = warp & 1;
    int gt0 = nh ? 12 : 0;
    int ngt = nh ? 13 : 12;

    float sacc[13][4];
    #pragma unroll
    for (int t = 0; t < 13; t++)
        #pragma unroll
        for (int i = 0; i < 4; i++) sacc[t][i] = 0.f;

    #pragma unroll
    for (int kk = 0; kk < 32; kk += 8) {
        uint32_t af[4];
        int r = mt * 16 + grp;
        af[0] = Qs[r][kk + qk];     af[1] = Qs[r + 8][kk + qk];
        af[2] = Qs[r][kk + qk + 4]; af[3] = Qs[r + 8][kk + qk + 4];
        #pragma unroll
        for (int t = 0; t < 13; t++) {
            if (t < ngt) {
                int gt = gt0 + t;
                uint32_t bf[2];
                bf[0] = Ks[kk + qk][gt * 8 + grp];
                bf[1] = Ks[kk + qk + 4][gt * 8 + grp];
                mma_tf32(sacc[t], af, bf);
            }
        }
    }

    // ---- scatter: valid -> score+rpb; invalid -> 0.0f (already "exp'd") ----
    {
        int r0 = mt * 16 + grp, r1 = r0 + 8;
        int i_a = i0 + (r0 >> 3), j_a = j0 + (r0 & 7);
        int ni_a = i_a - 3; ni_a = ni_a < 0 ? 0 : (ni_a > 57 ? 57 : ni_a);
        int nj_a = j_a - 3; nj_a = nj_a < 0 ? 0 : (nj_a > 57 ? 57 : nj_a);
        int di_a = ni_a - wi0, dj_a = nj_a - wj0;
        int rb_a = (ni_a - i_a + 6) * 13 + (nj_a - j_a + 6);
        int i_b = i0 + (r1 >> 3), j_b = j0 + (r1 & 7);
        int ni_b = i_b - 3; ni_b = ni_b < 0 ? 0 : (ni_b > 57 ? 57 : ni_b);
        int nj_b = j_b - 3; nj_b = nj_b < 0 ? 0 : (nj_b > 57 ? 57 : nj_b);
        int di_b = ni_b - wi0, dj_b = nj_b - wj0;
        int rb_b = (ni_b - i_b + 6) * 13 + (nj_b - j_b + 6);

        #pragma unroll
        for (int t = 0; t < 13; t++) {
            if (t >= ngt) break;
            int gt = gt0 + t;
            #pragma unroll
            for (int cc = 0; cc < 2; cc++) {
                int col = gt * 8 + 2 * qk + cc;
                int rw = (col * 2341) >> 15;
                int cw = col - rw * 14;
                int a0 = rw - di_a, b0 = cw - dj_a;
                uint32_t v0 = ((unsigned)a0 < 7u && (unsigned)b0 < 7u)
                         ? __float_as_uint(sacc[t][cc] + srpb[rb_a + a0 * 13 + b0]) : 0u;
                P[r0][col] = v0;
                int a1 = rw - di_b, b1 = cw - dj_b;
                uint32_t v1 = ((unsigned)a1 < 7u && (unsigned)b1 < 7u)
                         ? __float_as_uint(sacc[t][2 + cc] + srpb[rb_b + a1 * 13 + b1]) : 0u;
                P[r1][col] = v1;
            }
        }
    }
    __syncthreads();

    #pragma unroll
    for (int idx = tid; idx < 200 * 32; idx += 256) {
        int widx = idx >> 5, c = idx & 31;
        int rw = (widx * 2341) >> 15; rw = rw > 13 ? 13 : rw;
        int cw = widx - rw * 14;
        int gi = wi0 + rw; gi = gi > 63 ? 63 : gi;
        int gj = wj0 + cw; gj = gj > 63 ? 63 : gj;
        Vs[widx][c] = f2tf32(qb[(size_t)(gi * 64 + gj) * 384 + 256 + c]);
    }

    // ---- sparse softmax: only the 49 valid entries per pixel ----
    {
        int p0w = warp * 8;
        #pragma unroll
        for (int pp = 0; pp < 8; pp++) {
            int p = p0w + pp;
            int i = i0 + (p >> 3), j = j0 + (p & 7);
            int ni = i - 3; ni = ni < 0 ? 0 : (ni > 57 ? 57 : ni);
            int nj = j - 3; nj = nj < 0 ? 0 : (nj > 57 ? 57 : nj);
            int wbase = (ni - wi0) * 14 + (nj - wj0);

            int a0 = (lane * 9363) >> 16, b0 = lane - a0 * 7;
            int col0 = wbase + a0 * 14 + b0;
            float v0 = __uint_as_float(P[p][col0]);
            int e1 = lane + 32;
            int a1 = (e1 * 9363) >> 16, b1 = e1 - a1 * 7;
            int col1 = wbase + a1 * 14 + b1;
            bool has1 = lane < 17;
            float v1 = has1 ? __uint_as_float(P[p][col1]) : -1e30f;

            float m = fmaxf(v0, v1);
            #pragma unroll
            for (int o = 16; o > 0; o >>= 1) m = fmaxf(m, __shfl_xor_sync(0xffffffffu, m, o));
            float ex0 = __expf(v0 - m);
            float ex1 = has1 ? __expf(v1 - m) : 0.f;
            float s = ex0 + ex1;
            #pragma unroll
            for (int o = 16; o > 0; o >>= 1) s += __shfl_xor_sync(0xffffffffu, s, o);
            P[p][col0] = f2tf32(ex0);
            if (has1) P[p][col1] = f2tf32(ex1);
            if (lane == 0) sinv[p] = 1.0f / s;
        }
    }
    __syncthreads();

    float oacc[2][4];
    #pragma unroll
    for (int nt = 0; nt < 2; nt++)
        #pragma unroll
        for (int i = 0; i < 4; i++) oacc[nt][i] = 0.f;

    int c0 = nh * 16;
    for (int kt = 0; kt < 200; kt += 8) {
        uint32_t af[4];
        int r = mt * 16 + grp;
        af[0] = P[r][kt + qk];     af[1] = P[r + 8][kt + qk];
        af[2] = P[r][kt + qk + 4]; af[3] = P[r + 8][kt + qk + 4];
        #pragma unroll
        for (int nt = 0; nt < 2; nt++) {
            uint32_t bf[2];
            bf[0] = Vs[kt + qk][c0 + nt * 8 + grp];
            bf[1] = Vs[kt + qk + 4][c0 + nt * 8 + grp];
            mma_tf32(oacc[nt], af, bf);
        }
    }

    {
        int r0 = mt * 16 + grp, r1 = r0 + 8;
        float inv0 = sinv[r0], inv1 = sinv[r1];
        int ia = i0 + (r0 >> 3), ja = j0 + (r0 & 7);
        int ib = i0 + (r1 >> 3), jb = j0 + (r1 & 7);
        size_t oa = (size_t)(n * HWP + ia * 64 + ja) * CDIM + h * DH;
        size_t ob = (size_t)(n * HWP + ib * 64 + jb) * CDIM + h * DH;
        #pragma unroll
        for (int nt = 0; nt < 2; nt++) {
            int cc0 = c0 + nt * 8 + 2 * qk;
            na[oa + cc0]     = oacc[nt][0] * inv0;
            na[oa + cc0 + 1] = oacc[nt][1] * inv0;
            na[ob + cc0]     = oacc[nt][2] * inv1;
            na[ob + cc0 + 1] = oacc[nt][3] * inv1;
        }
    }
}

// ---------------------------------------------------------------------------
// Fused proj GEMM (bf16) + channel-attn gate + residual combine + LayerNorm2.
// BM=64 (R11 proven version).
// ---------------------------------------------------------------------------
__global__ __launch_bounds__(128)
void k_proj_ln(const float* __restrict__ A /*na*/, const float* __restrict__ B /*proj_w*/,
               const float* __restrict__ bias,
               const float* __restrict__ xs, const float* __restrict__ t,
               const float* __restrict__ gsum,
               const float* __restrict__ ca1w, const float* __restrict__ ca1b,
               const float* __restrict__ ca2w, const float* __restrict__ ca2b,
               const float* __restrict__ w2, const float* __restrict__ b2,
               float* __restrict__ x2, float* __restrict__ xn2)
{
    __shared__ union SU {
        struct { uint32_t Asp[64][20]; uint32_t Bsp[16][136]; } gm;
        float x2s[64][132];
    } sm;
    __shared__ float sgm[CDIM];
    __shared__ float sr7[7];
    __shared__ float sgarr[CDIM];

    int tid  = threadIdx.x;
    int lane = tid & 31;
    int warp = tid >> 5;
    int grp = lane >> 2, qk = lane & 3;
    int m0 = blockIdx.x * 64;
    int n = m0 >> 12;

    float acc[16][4];
    #pragma unroll
    for (int nt = 0; nt < 16; nt++)
        #pragma unroll
        for (int i = 0; i < 4; i++) acc[nt][i] = 0.f;

    int arow = tid >> 1, kseg = (tid & 1) * 16, apair = (tid & 1) * 8;
    int pr = tid >> 3, bc = (tid & 7) * 16;

    for (int k0 = 0; k0 < 128; k0 += 32) {
        const float* ap = A + (size_t)(m0 + arow) * CDIM + k0 + kseg;
        float4 a0 = *(const float4*)ap,       a1 = *(const float4*)(ap + 4);
        float4 a2 = *(const float4*)(ap + 8), a3 = *(const float4*)(ap + 12);
        sm.gm.Asp[arow][apair + 0] = pack_bf16(a0.x, a0.y);
        sm.gm.Asp[arow][apair + 1] = pack_bf16(a0.z, a0.w);
        sm.gm.Asp[arow][apair + 2] = pack_bf16(a1.x, a1.y);
        sm.gm.Asp[arow][apair + 3] = pack_bf16(a1.z, a1.w);
        sm.gm.Asp[arow][apair + 4] = pack_bf16(a2.x, a2.y);
        sm.gm.Asp[arow][apair + 5] = pack_bf16(a2.z, a2.w);
        sm.gm.Asp[arow][apair + 6] = pack_bf16(a3.x, a3.y);
        sm.gm.Asp[arow][apair + 7] = pack_bf16(a3.z, a3.w);

        const float* bp = B + (size_t)(k0 + 2 * pr) * CDIM + bc;
        #pragma unroll
        for (int i = 0; i < 4; i++) {
            float4 ev = *(const float4*)(bp + i * 4);
            float4 ov = *(const float4*)(bp + CDIM + i * 4);
            sm.gm.Bsp[pr][bc + i * 4 + 0] = pack_bf16(ev.x, ov.x);
            sm.gm.Bsp[pr][bc + i * 4 + 1] = pack_bf16(ev.y, ov.y);
            sm.gm.Bsp[pr][bc + i * 4 + 2] = pack_bf16(ev.z, ov.z);
            sm.gm.Bsp[pr][bc + i * 4 + 3] = pack_bf16(ev.w, ov.w);
        }
        __syncthreads();
        #pragma unroll
        for (int ks = 0; ks < 2; ks++) {
            int pb8 = ks * 8;
            uint32_t af[4];
            int r = warp * 16 + grp;
            af[0] = sm.gm.Asp[r][pb8 + qk];     af[1] = sm.gm.Asp[r + 8][pb8 + qk];
            af[2] = sm.gm.Asp[r][pb8 + qk + 4]; af[3] = sm.gm.Asp[r + 8][pb8 + qk + 4];
            #pragma unroll
            for (int nt = 0; nt < 16; nt++) {
                uint32_t bf[2];
                bf[0] = sm.gm.Bsp[pb8 + qk][nt * 8 + grp];
                bf[1] = sm.gm.Bsp[pb8 + qk + 4][nt * 8 + grp];
                mma_bf16_k16(acc[nt], af, bf);
            }
        }
        __syncthreads();
    }

    // ---- channel-attention gate in-block ----
    sgm[tid] = gsum[n * CDIM + tid] * (1.0f / HWP);
    __syncthreads();
    if (warp == 0) {
        float part[7];
        #pragma unroll
        for (int j = 0; j < 7; j++) part[j] = 0.f;
        #pragma unroll
        for (int k = 0; k < 4; k++) {
            int c = lane + 32 * k;
            float gv = sgm[c];
            #pragma unroll
            for (int j = 0; j < 7; j++) part[j] += gv * ca1w[c * 7 + j];
        }
        #pragma unroll
        for (int j = 0; j < 7; j++) {
            #pragma unroll
            for (int o = 16; o > 0; o >>= 1)
                part[j] += __shfl_xor_sync(0xffffffffu, part[j], o);
        }
        if (lane == 0) {
            #pragma unroll
            for (int j = 0; j < 7; j++) sr7[j] = fmaxf(part[j] + ca1b[j], 0.f);
        }
    }
    __syncthreads();
    {
        float s = ca2b[tid];
        #pragma unroll
        for (int j = 0; j < 7; j++) s += sr7[j] * ca2w[j * CDIM + tid];
        sgarr[tid] = (1.0f / (1.0f + expf(-s))) * 0.02f;
    }
    __syncthreads();

    {
        int r = warp * 16 + grp;
        size_t ro0 = (size_t)(m0 + r) * CDIM;
        size_t ro1 = (size_t)(m0 + r + 8) * CDIM;
        #pragma unroll
        for (int nt = 0; nt < 16; nt++) {
            int c = nt * 8 + 2 * qk;
            float bb0 = bias[c], bb1 = bias[c + 1];
            float g0 = sgarr[c], g1 = sgarr[c + 1];
            sm.x2s[r][c]         = acc[nt][0] + bb0 + xs[ro0 + c]     + t[ro0 + c]     * g0;
            sm.x2s[r][c + 1]     = acc[nt][1] + bb1 + xs[ro0 + c + 1] + t[ro0 + c + 1] * g1;
            sm.x2s[r + 8][c]     = acc[nt][2] + bb0 + xs[ro1 + c]     + t[ro1 + c]     * g0;
            sm.x2s[r + 8][c + 1] = acc[nt][3] + bb1 + xs[ro1 + c + 1] + t[ro1 + c + 1] * g1;
        }
    }
    __syncthreads();

    float w2r[4], b2r[4];
    #pragma unroll
    for (int k = 0; k < 4; k++) { w2r[k] = w2[lane + 32 * k]; b2r[k] = b2[lane + 32 * k]; }

    #pragma unroll
    for (int rr = 0; rr < 16; rr++) {
        int r = warp * 16 + rr;
        float v[4];
        float sum = 0.f, sq = 0.f;
        #pragma unroll
        for (int k = 0; k < 4; k++) {
            v[k] = sm.x2s[r][lane + 32 * k];
            sum += v[k]; sq += v[k] * v[k];
        }
        #pragma unroll
        for (int o = 16; o > 0; o >>= 1) {
            sum += __shfl_xor_sync(0xffffffffu, sum, o);
            sq  += __shfl_xor_sync(0xffffffffu, sq, o);
        }
        float mu = sum * (1.0f / CDIM);
        float rs = rsqrtf(sq * (1.0f / CDIM) - mu * mu + 1e-5f);
        size_t ro = (size_t)(m0 + r) * CDIM;
        #pragma unroll
        for (int k = 0; k < 4; k++) {
            x2[ro + lane + 32 * k]  = v[k];
            xn2[ro + lane + 32 * k] = (v[k] - mu) * rs * w2r[k] + b2r[k];
        }
    }
}

// ---------------------------------------------------------------------------
// Launch — conv forked onto a second stream, overlapping qkv + NA.
// Stream/events created once on the first (uncaptured correctness) call;
// no device memory is allocated. The captured graph contains the fork/join
// as parallel branches.
// ---------------------------------------------------------------------------
extern "C" void kernel_launch(void* const* d_in, const int* in_sizes, int n_in,
                              void* d_out, int out_size)
{
    const float* x      = (const float*)d_in[0];
    const float* ln1_w  = (const float*)d_in[1];
    const float* ln1_b  = (const float*)d_in[2];
    const float* ln2_w  = (const float*)d_in[3];
    const float* ln2_b  = (const float*)d_in[4];
    const float* qkv_w  = (const float*)d_in[5];
    const float* qkv_b  = (const float*)d_in[6];
    const float* proj_w = (const float*)d_in[7];
    const float* proj_b = (const float*)d_in[8];
    const float* rpb    = (const float*)d_in[9];
    const float* conv1_w= (const float*)d_in[10];
    const float* conv1_b= (const float*)d_in[11];
    const float* conv2_w= (const float*)d_in[12];
    const float* conv2_b= (const float*)d_in[13];
    const float* ca1_w  = (const float*)d_in[14];
    const float* ca1_b  = (const float*)d_in[15];
    const float* ca2_w  = (const float*)d_in[16];
    const float* ca2_b  = (const float*)d_in[17];
    const float* fc1_w  = (const float*)d_in[18];
    const float* fc1_b  = (const float*)d_in[19];
    const float* fc2_w  = (const float*)d_in[20];
    const float* fc2_b  = (const float*)d_in[21];
    float* out = (float*)d_out;

    float* scr = nullptr;
    cudaGetSymbolAddress((void**)&scr, d_scratch);
    float* xs   = scr + OFF_XS;
    float* xn   = scr + OFF_XN;
    float* qkv  = scr + OFF_QKV;
    float* t    = scr + OFF_T;
    float* na   = scr + OFF_NA;
    float* x2   = scr + OFF_X2;
    float* xn2  = scr + OFF_XN2;
    float* h1   = scr + OFF_H1;
    float* gsum = scr + OFF_GSUM;

    cudaFuncSetAttribute(k_na, cudaFuncAttributeMaxDynamicSharedMemorySize, NA_SMEM);

    static cudaStream_t s2 = nullptr;
    static cudaEvent_t ev_fork = nullptr, ev_join = nullptr;
    if (s2 == nullptr) {
        cudaStreamCreateWithFlags(&s2, cudaStreamNonBlocking);
        cudaEventCreateWithFlags(&ev_fork, cudaEventDisableTiming);
        cudaEventCreateWithFlags(&ev_join, cudaEventDisableTiming);
    }

    // 1. transpose + LN1 (+ zero gsum)
    k_transpose_ln<<<ROWS / 32, 128>>>(x, ln1_w, ln1_b, xs, xn, gsum);

    // fork: conv path on s2 (depends only on xn/gsum)
    cudaEventRecord(ev_fork, 0);
    cudaStreamWaitEvent(s2, ev_fork, 0);
    k_conv<<<ROWS / 64, 128, 0, s2>>>(xn, conv1_w, conv1_b, conv2_w, conv2_b, t, gsum);
    cudaEventRecord(ev_join, s2);

    // main branch: qkv -> na
    k_mma_bf16<EPI_NONE><<<dim3(6, ROWS / 64), 128>>>(xn, qkv_w, qkv_b, qkv,
                                                      ROWS, 384, 128, nullptr);
    k_na<<<dim3(64, NB * NHEAD), 256, NA_SMEM>>>(qkv, rpb, na);

    // join: proj needs na (main) + t/gsum (s2)
    cudaStreamWaitEvent(0, ev_join, 0);

    // 5. fused proj (bf16) + gate + residual + LN2
    k_proj_ln<<<ROWS / 64, 128>>>(na, proj_w, proj_b, xs, t, gsum,
                                  ca1_w, ca1_b, ca2_w, ca2_b,
                                  ln2_w, ln2_b, x2, xn2);
    // 6. fc1 + gelu (bf16): 16384 x 512 x 128
    k_mma_bf16<EPI_GELU><<<dim3(8, ROWS / 64), 128>>>(xn2, fc1_w, fc1_b, h1,
                                                      ROWS, 512, 128, nullptr);
    // 7. fc2 + residual (bf16), write NCHW output
    k_mma_bf16<EPI_OUT><<<dim3(2, ROWS / 64), 128>>>(h1, fc2_w, fc2_b, out,
                                                     ROWS, 128, 512, x2);
}

// round 15
// speedup vs baseline: 1.0595x; 1.0317x over previous
#include <cuda_runtime.h>
#include <cuda_bf16.h>
#include <math.h>
#include <stdint.h>

// ---------------------------------------------------------------------------
// Problem constants
// ---------------------------------------------------------------------------
#define NB    4
#define CDIM  128
#define HWP   4096           // 64*64
#define ROWS  (NB * HWP)     // 16384
#define NHEAD 4
#define DH    32
#define KS    7

// Scratch arena layout (floats)
#define OFF_XS    0u
#define OFF_XN    2097152u            // 16384*128
#define OFF_QKV   4194304u            // len 16384*384
#define OFF_T     11010048u           // len 16384*128
#define OFF_NA    13107200u
#define OFF_X2    15204352u
#define OFF_XN2   17301504u
#define OFF_H1    19398656u           // len 16384*512
#define OFF_GSUM  27787264u           // 512
#define SCRATCH_FLOATS 27788288u

__device__ float d_scratch[SCRATCH_FLOATS];

__device__ __forceinline__ float gelu_exact(float x) {
    return 0.5f * x * (1.0f + erff(x * 0.7071067811865476f));
}

__device__ __forceinline__ uint32_t f2tf32(float f) {
    uint32_t r;
    asm("cvt.rna.tf32.f32 %0, %1;" : "=r"(r) : "f"(f));
    return r;
}

__device__ __forceinline__ void mma_tf32(float d[4], const uint32_t a[4], const uint32_t b[2]) {
    asm volatile(
        "mma.sync.aligned.m16n8k8.row.col.f32.tf32.tf32.f32 "
        "{%0,%1,%2,%3},{%4,%5,%6,%7},{%8,%9},{%0,%1,%2,%3};\n"
        : "+f"(d[0]), "+f"(d[1]), "+f"(d[2]), "+f"(d[3])
        : "r"(a[0]), "r"(a[1]), "r"(a[2]), "r"(a[3]), "r"(b[0]), "r"(b[1]));
}

__device__ __forceinline__ void mma_bf16_k16(float d[4], const uint32_t a[4], const uint32_t b[2]) {
    asm volatile(
        "mma.sync.aligned.m16n8k16.row.col.f32.bf16.bf16.f32 "
        "{%0,%1,%2,%3},{%4,%5,%6,%7},{%8,%9},{%0,%1,%2,%3};\n"
        : "+f"(d[0]), "+f"(d[1]), "+f"(d[2]), "+f"(d[3])
        : "r"(a[0]), "r"(a[1]), "r"(a[2]), "r"(a[3]), "r"(b[0]), "r"(b[1]));
}

// pack (lo, hi) floats into bf16x2 (lo in lower 16 bits = lower k index)
__device__ __forceinline__ uint32_t pack_bf16(float lo, float hi) {
    uint32_t r;
    asm("cvt.rn.bf16x2.f32 %0, %1, %2;" : "=r"(r) : "f"(hi), "f"(lo));
    return r;
}

// ---------------------------------------------------------------------------
// Kernel 1: NCHW -> NHWC transpose + LayerNorm1.  32 pixels per block.
// ---------------------------------------------------------------------------
__global__ __launch_bounds__(128)
void k_transpose_ln(const float* __restrict__ x,
                    const float* __restrict__ w, const float* __restrict__ b,
                    float* __restrict__ xs, float* __restrict__ xn,
                    float* __restrict__ gsum)
{
    __shared__ float s[32][129];
    __shared__ float smu[32], srs[32];
    int tid = threadIdx.x;
    if (blockIdx.x == 0) {
        #pragma unroll
        for (int i = 0; i < 4; i++) gsum[tid + i * 128] = 0.f;
    }
    int row0 = blockIdx.x * 32;
    int n  = row0 >> 12;
    int p0 = row0 & 4095;
    int pl = tid & 31;
    int cg = tid >> 5;       // 0..3

    #pragma unroll 4
    for (int it = 0; it < 32; it++) {
        int c = it * 4 + cg;
        s[pl][c] = x[((size_t)(n * CDIM + c) << 12) + p0 + pl];
    }
    __syncthreads();

    if (tid < 32) {
        float sum = 0.f, sq = 0.f;
        #pragma unroll 8
        for (int c = 0; c < CDIM; c++) { float v = s[tid][c]; sum += v; sq += v * v; }
        float mu  = sum * (1.0f / CDIM);
        float var = sq * (1.0f / CDIM) - mu * mu;
        smu[tid] = mu;
        srs[tid] = rsqrtf(var + 1e-5f);
    }
    __syncthreads();

    float wc = w[tid], bc = b[tid];
    #pragma unroll 4
    for (int it = 0; it < 32; it++) {
        float v = s[it][tid];
        size_t o = (size_t)(row0 + it) * CDIM + tid;
        xs[o] = v;
        xn[o] = (v - smu[it]) * srs[it] * wc + bc;
    }
}

// ---------------------------------------------------------------------------
// Epilogue helpers
// ---------------------------------------------------------------------------
#define EPI_NONE 0
#define EPI_GELU 1
#define EPI_OUT  3   // out NCHW = acc+bias + e1(x2)

template<int EPI>
__device__ __forceinline__ void epi_write(float* __restrict__ C, int row, int col,
                                          int N, float v, const float* __restrict__ e1)
{
    if (EPI == EPI_GELU) {
        C[(size_t)row * N + col] = gelu_exact(v);
    } else if (EPI == EPI_NONE) {
        C[(size_t)row * N + col] = v;
    } else { // EPI_OUT: write NCHW
        v += e1[(size_t)row * CDIM + col];
        int bn = row >> 12, p = row & 4095;
        C[((size_t)(bn * CDIM + col) << 12) + p] = v;
    }
}

// ---------------------------------------------------------------------------
// Pipelined bf16 GEMM (m16n8k16): BM=64, BN=64, BK=32, 128 threads.
// ---------------------------------------------------------------------------
template<int EPI>
__global__ __launch_bounds__(128)
void k_mma_bf16(const float* __restrict__ A, const float* __restrict__ B,
                const float* __restrict__ bias, float* __restrict__ C,
                int M, int N, int K, const float* __restrict__ e1)
{
    constexpr int BM = 64, BN = 64, BK = 32;
    __shared__ uint32_t Asp[BM][20];
    __shared__ uint32_t Bsp[BK / 2][72];

    int tid  = threadIdx.x;
    int lane = tid & 31;
    int warp = tid >> 5;
    int wm = warp & 1, wn = warp >> 1;
    int m0 = blockIdx.y * BM, n0 = blockIdx.x * BN;
    int grp = lane >> 2, qk = lane & 3;

    float d[2][4][4];
    #pragma unroll
    for (int mt = 0; mt < 2; mt++)
        #pragma unroll
        for (int nt = 0; nt < 4; nt++)
            #pragma unroll
            for (int i = 0; i < 4; i++) d[mt][nt][i] = 0.f;

    int arow = tid >> 1, kseg = (tid & 1) * 16, apair = (tid & 1) * 8;
    int pr = tid >> 3, bc = (tid & 7) * 8;     // B: pair-row, col base

    float4 pa0, pa1, pa2, pa3, pb0, pb1, pb2, pb3;

#define LDG_TILE(k0) { \
    const float* ap = A + (size_t)(m0 + arow) * K + (k0) + kseg; \
    pa0 = *(const float4*)ap;       pa1 = *(const float4*)(ap + 4); \
    pa2 = *(const float4*)(ap + 8); pa3 = *(const float4*)(ap + 12); \
    const float* bp = B + (size_t)((k0) + 2 * pr) * N + n0 + bc; \
    pb0 = *(const float4*)bp;       pb1 = *(const float4*)(bp + 4); \
    pb2 = *(const float4*)(bp + N); pb3 = *(const float4*)(bp + N + 4); }

#define STS_TILE() { \
    Asp[arow][apair+0]=pack_bf16(pa0.x,pa0.y); Asp[arow][apair+1]=pack_bf16(pa0.z,pa0.w); \
    Asp[arow][apair+2]=pack_bf16(pa1.x,pa1.y); Asp[arow][apair+3]=pack_bf16(pa1.z,pa1.w); \
    Asp[arow][apair+4]=pack_bf16(pa2.x,pa2.y); Asp[arow][apair+5]=pack_bf16(pa2.z,pa2.w); \
    Asp[arow][apair+6]=pack_bf16(pa3.x,pa3.y); Asp[arow][apair+7]=pack_bf16(pa3.z,pa3.w); \
    Bsp[pr][bc+0]=pack_bf16(pb0.x,pb2.x); Bsp[pr][bc+1]=pack_bf16(pb0.y,pb2.y); \
    Bsp[pr][bc+2]=pack_bf16(pb0.z,pb2.z); Bsp[pr][bc+3]=pack_bf16(pb0.w,pb2.w); \
    Bsp[pr][bc+4]=pack_bf16(pb1.x,pb3.x); Bsp[pr][bc+5]=pack_bf16(pb1.y,pb3.y); \
    Bsp[pr][bc+6]=pack_bf16(pb1.z,pb3.z); Bsp[pr][bc+7]=pack_bf16(pb1.w,pb3.w); }

#define MMA_TILE() { \
    _Pragma("unroll") \
    for (int ks = 0; ks < 2; ks++) { \
        int pb8 = ks * 8; \
        uint32_t af[2][4], bf[4][2]; \
        _Pragma("unroll") \
        for (int mt = 0; mt < 2; mt++) { \
            int r = wm * 32 + mt * 16 + grp; \
            af[mt][0] = Asp[r][pb8 + qk];     af[mt][1] = Asp[r + 8][pb8 + qk]; \
            af[mt][2] = Asp[r][pb8 + qk + 4]; af[mt][3] = Asp[r + 8][pb8 + qk + 4]; \
        } \
        _Pragma("unroll") \
        for (int nt = 0; nt < 4; nt++) { \
            int cidx = wn * 32 + nt * 8 + grp; \
            bf[nt][0] = Bsp[pb8 + qk][cidx]; bf[nt][1] = Bsp[pb8 + qk + 4][cidx]; \
        } \
        _Pragma("unroll") \
        for (int mt = 0; mt < 2; mt++) \
            _Pragma("unroll") \
            for (int nt = 0; nt < 4; nt++) \
                mma_bf16_k16(d[mt][nt], af[mt], bf[nt]); \
    } }

    LDG_TILE(0);
    STS_TILE();
    __syncthreads();
    for (int k0 = BK; k0 < K; k0 += BK) {
        LDG_TILE(k0);
        MMA_TILE();
        __syncthreads();
        STS_TILE();
        __syncthreads();
    }
    MMA_TILE();

#undef LDG_TILE
#undef STS_TILE
#undef MMA_TILE

    #pragma unroll
    for (int mt = 0; mt < 2; mt++) {
        int rbase = m0 + wm * 32 + mt * 16 + grp;
        #pragma unroll
        for (int nt = 0; nt < 4; nt++) {
            int cbase = n0 + wn * 32 + nt * 8 + 2 * qk;
            float b0 = bias[cbase], b1 = bias[cbase + 1];
            epi_write<EPI>(C, rbase,     cbase,     N, d[mt][nt][0] + b0, e1);
            epi_write<EPI>(C, rbase,     cbase + 1, N, d[mt][nt][1] + b1, e1);
            epi_write<EPI>(C, rbase + 8, cbase,     N, d[mt][nt][2] + b0, e1);
            epi_write<EPI>(C, rbase + 8, cbase + 1, N, d[mt][nt][3] + b1, e1);
        }
    }
}

// ---------------------------------------------------------------------------
// Fused conv1 + GELU + conv2 + spatial-mean.
// 64 rows per block, 256 threads / 8 warps (4 row-warps x 2 col-warps).
// ---------------------------------------------------------------------------
__global__ __launch_bounds__(256)
void k_conv(const float* __restrict__ xn,
            const float* __restrict__ w1, const float* __restrict__ b1,
            const float* __restrict__ w2, const float* __restrict__ b2,
            float* __restrict__ tout, float* __restrict__ gsum)
{
    __shared__ uint32_t As[64][36];
    __shared__ uint32_t Bs1[32][40];
    __shared__ uint32_t St1[64][36];
    __shared__ uint32_t Bs2[32][136];

    int tid  = threadIdx.x;
    int lane = tid & 31;
    int warp = tid >> 5;
    int grp = lane >> 2, qk = lane & 3;
    int wm = warp & 3, wn = warp >> 2;
    int m0 = blockIdx.x * 64;

    // cache conv2_w (32 x 128) in smem once: 256 threads, 16 cols each
    {
        int r = tid >> 3, c0 = (tid & 7) * 16;
        #pragma unroll
        for (int i = 0; i < 4; i++) {
            float4 v = *(const float4*)(w2 + (size_t)r * 128 + c0 + i * 4);
            Bs2[r][c0 + i * 4 + 0] = f2tf32(v.x);
            Bs2[r][c0 + i * 4 + 1] = f2tf32(v.y);
            Bs2[r][c0 + i * 4 + 2] = f2tf32(v.z);
            Bs2[r][c0 + i * 4 + 3] = f2tf32(v.w);
        }
    }

    // ---- stage 1: t1 = xn @ w1 (64x32, K=128). Warp tile 16x16 ----
    float acc1[2][4];
    #pragma unroll
    for (int nt = 0; nt < 2; nt++)
        #pragma unroll
        for (int i = 0; i < 4; i++) acc1[nt][i] = 0.f;

    int arow = tid >> 2, kseg = (tid & 3) * 8;
    int b1row = tid >> 3, b1col = (tid & 7) * 4;

    for (int k0 = 0; k0 < 128; k0 += 32) {
        const float* ap = xn + (size_t)(m0 + arow) * CDIM + k0 + kseg;
        #pragma unroll
        for (int i = 0; i < 2; i++) {
            float4 v = *(const float4*)(ap + i * 4);
            As[arow][kseg + i * 4 + 0] = f2tf32(v.x);
            As[arow][kseg + i * 4 + 1] = f2tf32(v.y);
            As[arow][kseg + i * 4 + 2] = f2tf32(v.z);
            As[arow][kseg + i * 4 + 3] = f2tf32(v.w);
        }
        {
            float4 v = *(const float4*)(w1 + (size_t)(k0 + b1row) * 32 + b1col);
            Bs1[b1row][b1col + 0] = f2tf32(v.x);
            Bs1[b1row][b1col + 1] = f2tf32(v.y);
            Bs1[b1row][b1col + 2] = f2tf32(v.z);
            Bs1[b1row][b1col + 3] = f2tf32(v.w);
        }
        __syncthreads();
        #pragma unroll
        for (int kk = 0; kk < 32; kk += 8) {
            uint32_t af[4], bf[2][2];
            int r = wm * 16 + grp;
            af[0] = As[r][kk + qk];     af[1] = As[r + 8][kk + qk];
            af[2] = As[r][kk + qk + 4]; af[3] = As[r + 8][kk + qk + 4];
            #pragma unroll
            for (int nt = 0; nt < 2; nt++) {
                bf[nt][0] = Bs1[kk + qk][wn * 16 + nt * 8 + grp];
                bf[nt][1] = Bs1[kk + qk + 4][wn * 16 + nt * 8 + grp];
            }
            #pragma unroll
            for (int nt = 0; nt < 2; nt++) mma_tf32(acc1[nt], af, bf[nt]);
        }
        __syncthreads();
    }

    // stage-1 epilogue: gelu -> St1 (tf32)
    {
        int r = wm * 16 + grp;
        #pragma unroll
        for (int nt = 0; nt < 2; nt++) {
            int c = wn * 16 + nt * 8 + 2 * qk;
            float bb0 = b1[c], bb1 = b1[c + 1];
            St1[r][c]         = f2tf32(gelu_exact(acc1[nt][0] + bb0));
            St1[r][c + 1]     = f2tf32(gelu_exact(acc1[nt][1] + bb1));
            St1[r + 8][c]     = f2tf32(gelu_exact(acc1[nt][2] + bb0));
            St1[r + 8][c + 1] = f2tf32(gelu_exact(acc1[nt][3] + bb1));
        }
    }
    __syncthreads();

    // ---- stage 2: t = gelu(t1) @ w2 (64x128, K=32). Warp tile 16x64 ----
    float acc2[8][4];
    #pragma unroll
    for (int nt = 0; nt < 8; nt++)
        #pragma unroll
        for (int i = 0; i < 4; i++) acc2[nt][i] = 0.f;

    #pragma unroll
    for (int kk = 0; kk < 32; kk += 8) {
        uint32_t af[4];
        int r = wm * 16 + grp;
        af[0] = St1[r][kk + qk];     af[1] = St1[r + 8][kk + qk];
        af[2] = St1[r][kk + qk + 4]; af[3] = St1[r + 8][kk + qk + 4];
        #pragma unroll
        for (int nt = 0; nt < 8; nt++) {
            uint32_t bf[2];
            bf[0] = Bs2[kk + qk][wn * 64 + nt * 8 + grp];
            bf[1] = Bs2[kk + qk + 4][wn * 64 + nt * 8 + grp];
            mma_tf32(acc2[nt], af, bf);
        }
    }

    int n = m0 >> 12;
    int r = wm * 16 + grp;
    #pragma unroll
    for (int nt = 0; nt < 8; nt++) {
        int c = wn * 64 + nt * 8 + 2 * qk;
        float bb0 = b2[c], bb1 = b2[c + 1];
        float v0 = acc2[nt][0] + bb0, v1 = acc2[nt][1] + bb1;
        float v2 = acc2[nt][2] + bb0, v3 = acc2[nt][3] + bb1;
        size_t ro = (size_t)(m0 + r) * CDIM;
        tout[ro + c] = v0;             tout[ro + c + 1] = v1;
        tout[ro + 8 * CDIM + c] = v2;  tout[ro + 8 * CDIM + c + 1] = v3;
        float s0 = v0 + v2, s1 = v1 + v3;
        #pragma unroll
        for (int o = 4; o < 32; o <<= 1) {
            s0 += __shfl_xor_sync(0xffffffffu, s0, o);
            s1 += __shfl_xor_sync(0xffffffffu, s1, o);
        }
        if (lane < 4) {
            atomicAdd(&gsum[n * CDIM + c], s0);
            atomicAdd(&gsum[n * CDIM + c + 1], s1);
        }
    }
}

// ---------------------------------------------------------------------------
// Neighborhood attention — tensor-core tf32; sparse softmax.
// ---------------------------------------------------------------------------
#define NA_P_OFF   0
#define NA_Q_OFF   52224
#define NA_K_OFF   61440
#define NA_V_OFF   52224
#define NA_RPB_OFF 87552
#define NA_INV_OFF 88228
#define NA_SMEM    88512

__global__ __launch_bounds__(256)
void k_na(const float* __restrict__ qkv, const float* __restrict__ rpb,
          float* __restrict__ na)
{
    extern __shared__ char smem[];
    uint32_t (*P)[204]  = (uint32_t(*)[204])(smem + NA_P_OFF);
    uint32_t (*Qs)[36]  = (uint32_t(*)[36])(smem + NA_Q_OFF);
    uint32_t (*Ks)[204] = (uint32_t(*)[204])(smem + NA_K_OFF);
    uint32_t (*Vs)[40]  = (uint32_t(*)[40])(smem + NA_V_OFF);
    float* srpb = (float*)(smem + NA_RPB_OFF);
    float* sinv = (float*)(smem + NA_INV_OFF);

    int tid  = threadIdx.x;
    int lane = tid & 31;
    int warp = tid >> 5;
    int grp = lane >> 2, qk = lane & 3;

    int n = blockIdx.y >> 2;
    int h = blockIdx.y & 3;
    int i0 = (blockIdx.x >> 3) * 8, j0 = (blockIdx.x & 7) * 8;
    int wi0 = i0 - 3; wi0 = wi0 < 0 ? 0 : wi0;
    int wj0 = j0 - 3; wj0 = wj0 < 0 ? 0 : wj0;

    if (tid < 169) srpb[tid] = rpb[h * 169 + tid];

    const float* qb = qkv + (size_t)(n * HWP) * 384 + h * DH;

    #pragma unroll
    for (int idx = tid; idx < 64 * 32; idx += 256) {
        int p = idx >> 5, c = idx & 31;
        int i = i0 + (p >> 3), j = j0 + (p & 7);
        Qs[p][c] = f2tf32(qb[(size_t)(i * 64 + j) * 384 + c] * 0.17677669529663687f);
    }
    for (int idx = tid; idx < 8 * 200; idx += 256) {
        int chunk = idx / 200;
        int widx  = idx - chunk * 200;
        int c0 = chunk * 4;
        int rw = (widx * 2341) >> 15; rw = rw > 13 ? 13 : rw;
        int cw = widx - rw * 14;
        int gi = wi0 + rw; gi = gi > 63 ? 63 : gi;
        int gj = wj0 + cw; gj = gj > 63 ? 63 : gj;
        float4 v = *(const float4*)(qb + (size_t)(gi * 64 + gj) * 384 + 128 + c0);
        Ks[c0 + 0][widx] = f2tf32(v.x);
        Ks[c0 + 1][widx] = f2tf32(v.y);
        Ks[c0 + 2][widx] = f2tf32(v.z);
        Ks[c0 + 3][widx] = f2tf32(v.w);
    }
    __syncthreads();

    int mt = warp >> 1;
    int nh = warp & 1;
    int gt0 = nh ? 12 : 0;
    int ngt = nh ? 13 : 12;

    float sacc[13][4];
    #pragma unroll
    for (int t = 0; t < 13; t++)
        #pragma unroll
        for (int i = 0; i < 4; i++) sacc[t][i] = 0.f;

    #pragma unroll
    for (int kk = 0; kk < 32; kk += 8) {
        uint32_t af[4];
        int r = mt * 16 + grp;
        af[0] = Qs[r][kk + qk];     af[1] = Qs[r + 8][kk + qk];
        af[2] = Qs[r][kk + qk + 4]; af[3] = Qs[r + 8][kk + qk + 4];
        #pragma unroll
        for (int t = 0; t < 13; t++) {
            if (t < ngt) {
                int gt = gt0 + t;
                uint32_t bf[2];
                bf[0] = Ks[kk + qk][gt * 8 + grp];
                bf[1] = Ks[kk + qk + 4][gt * 8 + grp];
                mma_tf32(sacc[t], af, bf);
            }
        }
    }

    // ---- scatter: valid -> score+rpb; invalid -> 0.0f (already "exp'd") ----
    {
        int r0 = mt * 16 + grp, r1 = r0 + 8;
        int i_a = i0 + (r0 >> 3), j_a = j0 + (r0 & 7);
        int ni_a = i_a - 3; ni_a = ni_a < 0 ? 0 : (ni_a > 57 ? 57 : ni_a);
        int nj_a = j_a - 3; nj_a = nj_a < 0 ? 0 : (nj_a > 57 ? 57 : nj_a);
        int di_a = ni_a - wi0, dj_a = nj_a - wj0;
        int rb_a = (ni_a - i_a + 6) * 13 + (nj_a - j_a + 6);
        int i_b = i0 + (r1 >> 3), j_b = j0 + (r1 & 7);
        int ni_b = i_b - 3; ni_b = ni_b < 0 ? 0 : (ni_b > 57 ? 57 : ni_b);
        int nj_b = j_b - 3; nj_b = nj_b < 0 ? 0 : (nj_b > 57 ? 57 : nj_b);
        int di_b = ni_b - wi0, dj_b = nj_b - wj0;
        int rb_b = (ni_b - i_b + 6) * 13 + (nj_b - j_b + 6);

        #pragma unroll
        for (int t = 0; t < 13; t++) {
            if (t >= ngt) break;
            int gt = gt0 + t;
            #pragma unroll
            for (int cc = 0; cc < 2; cc++) {
                int col = gt * 8 + 2 * qk + cc;
                int rw = (col * 2341) >> 15;
                int cw = col - rw * 14;
                int a0 = rw - di_a, b0 = cw - dj_a;
                uint32_t v0 = ((unsigned)a0 < 7u && (unsigned)b0 < 7u)
                         ? __float_as_uint(sacc[t][cc] + srpb[rb_a + a0 * 13 + b0]) : 0u;
                P[r0][col] = v0;
                int a1 = rw - di_b, b1 = cw - dj_b;
                uint32_t v1 = ((unsigned)a1 < 7u && (unsigned)b1 < 7u)
                         ? __float_as_uint(sacc[t][2 + cc] + srpb[rb_b + a1 * 13 + b1]) : 0u;
                P[r1][col] = v1;
            }
        }
    }
    __syncthreads();

    #pragma unroll
    for (int idx = tid; idx < 200 * 32; idx += 256) {
        int widx = idx >> 5, c = idx & 31;
        int rw = (widx * 2341) >> 15; rw = rw > 13 ? 13 : rw;
        int cw = widx - rw * 14;
        int gi = wi0 + rw; gi = gi > 63 ? 63 : gi;
        int gj = wj0 + cw; gj = gj > 63 ? 63 : gj;
        Vs[widx][c] = f2tf32(qb[(size_t)(gi * 64 + gj) * 384 + 256 + c]);
    }

    // ---- sparse softmax: only the 49 valid entries per pixel ----
    {
        int p0w = warp * 8;
        #pragma unroll
        for (int pp = 0; pp < 8; pp++) {
            int p = p0w + pp;
            int i = i0 + (p >> 3), j = j0 + (p & 7);
            int ni = i - 3; ni = ni < 0 ? 0 : (ni > 57 ? 57 : ni);
            int nj = j - 3; nj = nj < 0 ? 0 : (nj > 57 ? 57 : nj);
            int wbase = (ni - wi0) * 14 + (nj - wj0);

            int a0 = (lane * 9363) >> 16, b0 = lane - a0 * 7;
            int col0 = wbase + a0 * 14 + b0;
            float v0 = __uint_as_float(P[p][col0]);
            int e1 = lane + 32;
            int a1 = (e1 * 9363) >> 16, b1 = e1 - a1 * 7;
            int col1 = wbase + a1 * 14 + b1;
            bool has1 = lane < 17;
            float v1 = has1 ? __uint_as_float(P[p][col1]) : -1e30f;

            float m = fmaxf(v0, v1);
            #pragma unroll
            for (int o = 16; o > 0; o >>= 1) m = fmaxf(m, __shfl_xor_sync(0xffffffffu, m, o));
            float ex0 = __expf(v0 - m);
            float ex1 = has1 ? __expf(v1 - m) : 0.f;
            float s = ex0 + ex1;
            #pragma unroll
            for (int o = 16; o > 0; o >>= 1) s += __shfl_xor_sync(0xffffffffu, s, o);
            P[p][col0] = f2tf32(ex0);
            if (has1) P[p][col1] = f2tf32(ex1);
            if (lane == 0) sinv[p] = 1.0f / s;
        }
    }
    __syncthreads();

    float oacc[2][4];
    #pragma unroll
    for (int nt = 0; nt < 2; nt++)
        #pragma unroll
        for (int i = 0; i < 4; i++) oacc[nt][i] = 0.f;

    int c0 = nh * 16;
    for (int kt = 0; kt < 200; kt += 8) {
        uint32_t af[4];
        int r = mt * 16 + grp;
        af[0] = P[r][kt + qk];     af[1] = P[r + 8][kt + qk];
        af[2] = P[r][kt + qk + 4]; af[3] = P[r + 8][kt + qk + 4];
        #pragma unroll
        for (int nt = 0; nt < 2; nt++) {
            uint32_t bf[2];
            bf[0] = Vs[kt + qk][c0 + nt * 8 + grp];
            bf[1] = Vs[kt + qk + 4][c0 + nt * 8 + grp];
            mma_tf32(oacc[nt], af, bf);
        }
    }

    {
        int r0 = mt * 16 + grp, r1 = r0 + 8;
        float inv0 = sinv[r0], inv1 = sinv[r1];
        int ia = i0 + (r0 >> 3), ja = j0 + (r0 & 7);
        int ib = i0 + (r1 >> 3), jb = j0 + (r1 & 7);
        size_t oa = (size_t)(n * HWP + ia * 64 + ja) * CDIM + h * DH;
        size_t ob = (size_t)(n * HWP + ib * 64 + jb) * CDIM + h * DH;
        #pragma unroll
        for (int nt = 0; nt < 2; nt++) {
            int cc0 = c0 + nt * 8 + 2 * qk;
            na[oa + cc0]     = oacc[nt][0] * inv0;
            na[oa + cc0 + 1] = oacc[nt][1] * inv0;
            na[ob + cc0]     = oacc[nt][2] * inv1;
            na[ob + cc0 + 1] = oacc[nt][3] * inv1;
        }
    }
}

// ---------------------------------------------------------------------------
// Fused proj GEMM (bf16) + gate + residual + LN2.
// BM=64, 256 threads / 8 warps (4 row-warps x 2 col-warps, warp tile 16x64).
// ---------------------------------------------------------------------------
__global__ __launch_bounds__(256)
void k_proj_ln(const float* __restrict__ A /*na*/, const float* __restrict__ B /*proj_w*/,
               const float* __restrict__ bias,
               const float* __restrict__ xs, const float* __restrict__ t,
               const float* __restrict__ gsum,
               const float* __restrict__ ca1w, const float* __restrict__ ca1b,
               const float* __restrict__ ca2w, const float* __restrict__ ca2b,
               const float* __restrict__ w2, const float* __restrict__ b2,
               float* __restrict__ x2, float* __restrict__ xn2)
{
    __shared__ union SU {
        struct { uint32_t Asp[64][20]; uint32_t Bsp[16][136]; } gm;
        float x2s[64][132];
    } sm;
    __shared__ float sgm[CDIM];
    __shared__ float sr7[7];
    __shared__ float sgarr[CDIM];

    int tid  = threadIdx.x;
    int lane = tid & 31;
    int warp = tid >> 5;
    int grp = lane >> 2, qk = lane & 3;
    int wm = warp & 3, wn = warp >> 2;
    int m0 = blockIdx.x * 64;
    int n = m0 >> 12;

    float acc[8][4];
    #pragma unroll
    for (int nt = 0; nt < 8; nt++)
        #pragma unroll
        for (int i = 0; i < 4; i++) acc[nt][i] = 0.f;

    int arow = tid >> 2, kseg = (tid & 3) * 8, apair = (tid & 3) * 4;
    int pr = tid >> 4, bc = (tid & 15) * 8;

    for (int k0 = 0; k0 < 128; k0 += 32) {
        const float* ap = A + (size_t)(m0 + arow) * CDIM + k0 + kseg;
        float4 a0 = *(const float4*)ap, a1 = *(const float4*)(ap + 4);
        sm.gm.Asp[arow][apair + 0] = pack_bf16(a0.x, a0.y);
        sm.gm.Asp[arow][apair + 1] = pack_bf16(a0.z, a0.w);
        sm.gm.Asp[arow][apair + 2] = pack_bf16(a1.x, a1.y);
        sm.gm.Asp[arow][apair + 3] = pack_bf16(a1.z, a1.w);

        const float* bp = B + (size_t)(k0 + 2 * pr) * CDIM + bc;
        #pragma unroll
        for (int i = 0; i < 2; i++) {
            float4 ev = *(const float4*)(bp + i * 4);
            float4 ov = *(const float4*)(bp + CDIM + i * 4);
            sm.gm.Bsp[pr][bc + i * 4 + 0] = pack_bf16(ev.x, ov.x);
            sm.gm.Bsp[pr][bc + i * 4 + 1] = pack_bf16(ev.y, ov.y);
            sm.gm.Bsp[pr][bc + i * 4 + 2] = pack_bf16(ev.z, ov.z);
            sm.gm.Bsp[pr][bc + i * 4 + 3] = pack_bf16(ev.w, ov.w);
        }
        __syncthreads();
        #pragma unroll
        for (int ks = 0; ks < 2; ks++) {
            int pb8 = ks * 8;
            uint32_t af[4];
            int r = wm * 16 + grp;
            af[0] = sm.gm.Asp[r][pb8 + qk];     af[1] = sm.gm.Asp[r + 8][pb8 + qk];
            af[2] = sm.gm.Asp[r][pb8 + qk + 4]; af[3] = sm.gm.Asp[r + 8][pb8 + qk + 4];
            #pragma unroll
            for (int nt = 0; nt < 8; nt++) {
                uint32_t bf[2];
                bf[0] = sm.gm.Bsp[pb8 + qk][wn * 64 + nt * 8 + grp];
                bf[1] = sm.gm.Bsp[pb8 + qk + 4][wn * 64 + nt * 8 + grp];
                mma_bf16_k16(acc[nt], af, bf);
            }
        }
        __syncthreads();
    }

    // ---- channel-attention gate in-block ----
    if (tid < CDIM) sgm[tid] = gsum[n * CDIM + tid] * (1.0f / HWP);
    __syncthreads();
    if (warp == 0) {
        float part[7];
        #pragma unroll
        for (int j = 0; j < 7; j++) part[j] = 0.f;
        #pragma unroll
        for (int k = 0; k < 4; k++) {
            int c = lane + 32 * k;
            float gv = sgm[c];
            #pragma unroll
            for (int j = 0; j < 7; j++) part[j] += gv * ca1w[c * 7 + j];
        }
        #pragma unroll
        for (int j = 0; j < 7; j++) {
            #pragma unroll
            for (int o = 16; o > 0; o >>= 1)
                part[j] += __shfl_xor_sync(0xffffffffu, part[j], o);
        }
        if (lane == 0) {
            #pragma unroll
            for (int j = 0; j < 7; j++) sr7[j] = fmaxf(part[j] + ca1b[j], 0.f);
        }
    }
    __syncthreads();
    if (tid < CDIM) {
        float s = ca2b[tid];
        #pragma unroll
        for (int j = 0; j < 7; j++) s += sr7[j] * ca2w[j * CDIM + tid];
        sgarr[tid] = (1.0f / (1.0f + expf(-s))) * 0.02f;
    }
    __syncthreads();

    // epilogue: x2 value -> smem
    {
        int r = wm * 16 + grp;
        size_t ro0 = (size_t)(m0 + r) * CDIM;
        size_t ro1 = (size_t)(m0 + r + 8) * CDIM;
        #pragma unroll
        for (int nt = 0; nt < 8; nt++) {
            int c = wn * 64 + nt * 8 + 2 * qk;
            float bb0 = bias[c], bb1 = bias[c + 1];
            float g0 = sgarr[c], g1 = sgarr[c + 1];
            sm.x2s[r][c]         = acc[nt][0] + bb0 + xs[ro0 + c]     + t[ro0 + c]     * g0;
            sm.x2s[r][c + 1]     = acc[nt][1] + bb1 + xs[ro0 + c + 1] + t[ro0 + c + 1] * g1;
            sm.x2s[r + 8][c]     = acc[nt][2] + bb0 + xs[ro1 + c]     + t[ro1 + c]     * g0;
            sm.x2s[r + 8][c + 1] = acc[nt][3] + bb1 + xs[ro1 + c + 1] + t[ro1 + c + 1] * g1;
        }
    }
    __syncthreads();

    float w2r[4], b2r[4];
    #pragma unroll
    for (int k = 0; k < 4; k++) { w2r[k] = w2[lane + 32 * k]; b2r[k] = b2[lane + 32 * k]; }

    #pragma unroll
    for (int rr = 0; rr < 8; rr++) {
        int r = warp * 8 + rr;
        float v[4];
        float sum = 0.f, sq = 0.f;
        #pragma unroll
        for (int k = 0; k < 4; k++) {
            v[k] = sm.x2s[r][lane + 32 * k];
            sum += v[k]; sq += v[k] * v[k];
        }
        #pragma unroll
        for (int o = 16; o > 0; o >>= 1) {
            sum += __shfl_xor_sync(0xffffffffu, sum, o);
            sq  += __shfl_xor_sync(0xffffffffu, sq, o);
        }
        float mu = sum * (1.0f / CDIM);
        float rs = rsqrtf(sq * (1.0f / CDIM) - mu * mu + 1e-5f);
        size_t ro = (size_t)(m0 + r) * CDIM;
        #pragma unroll
        for (int k = 0; k < 4; k++) {
            x2[ro + lane + 32 * k]  = v[k];
            xn2[ro + lane + 32 * k] = (v[k] - mu) * rs * w2r[k] + b2r[k];
        }
    }
}

// ---------------------------------------------------------------------------
// Launch — conv forked onto a second stream, overlapping qkv + NA.
// ---------------------------------------------------------------------------
extern "C" void kernel_launch(void* const* d_in, const int* in_sizes, int n_in,
                              void* d_out, int out_size)
{
    const float* x      = (const float*)d_in[0];
    const float* ln1_w  = (const float*)d_in[1];
    const float* ln1_b  = (const float*)d_in[2];
    const float* ln2_w  = (const float*)d_in[3];
    const float* ln2_b  = (const float*)d_in[4];
    const float* qkv_w  = (const float*)d_in[5];
    const float* qkv_b  = (const float*)d_in[6];
    const float* proj_w = (const float*)d_in[7];
    const float* proj_b = (const float*)d_in[8];
    const float* rpb    = (const float*)d_in[9];
    const float* conv1_w= (const float*)d_in[10];
    const float* conv1_b= (const float*)d_in[11];
    const float* conv2_w= (const float*)d_in[12];
    const float* conv2_b= (const float*)d_in[13];
    const float* ca1_w  = (const float*)d_in[14];
    const float* ca1_b  = (const float*)d_in[15];
    const float* ca2_w  = (const float*)d_in[16];
    const float* ca2_b  = (const float*)d_in[17];
    const float* fc1_w  = (const float*)d_in[18];
    const float* fc1_b  = (const float*)d_in[19];
    const float* fc2_w  = (const float*)d_in[20];
    const float* fc2_b  = (const float*)d_in[21];
    float* out = (float*)d_out;

    float* scr = nullptr;
    cudaGetSymbolAddress((void**)&scr, d_scratch);
    float* xs   = scr + OFF_XS;
    float* xn   = scr + OFF_XN;
    float* qkv  = scr + OFF_QKV;
    float* t    = scr + OFF_T;
    float* na   = scr + OFF_NA;
    float* x2   = scr + OFF_X2;
    float* xn2  = scr + OFF_XN2;
    float* h1   = scr + OFF_H1;
    float* gsum = scr + OFF_GSUM;

    cudaFuncSetAttribute(k_na, cudaFuncAttributeMaxDynamicSharedMemorySize, NA_SMEM);

    static cudaStream_t s2 = nullptr;
    static cudaEvent_t ev_fork = nullptr, ev_join = nullptr;
    if (s2 == nullptr) {
        cudaStreamCreateWithFlags(&s2, cudaStreamNonBlocking);
        cudaEventCreateWithFlags(&ev_fork, cudaEventDisableTiming);
        cudaEventCreateWithFlags(&ev_join, cudaEventDisableTiming);
    }

    // 1. transpose + LN1 (+ zero gsum)
    k_transpose_ln<<<ROWS / 32, 128>>>(x, ln1_w, ln1_b, xs, xn, gsum);

    // fork: conv path on s2 (depends only on xn/gsum)
    cudaEventRecord(ev_fork, 0);
    cudaStreamWaitEvent(s2, ev_fork, 0);
    k_conv<<<ROWS / 64, 256, 0, s2>>>(xn, conv1_w, conv1_b, conv2_w, conv2_b, t, gsum);
    cudaEventRecord(ev_join, s2);

    // main branch: qkv -> na
    k_mma_bf16<EPI_NONE><<<dim3(6, ROWS / 64), 128>>>(xn, qkv_w, qkv_b, qkv,
                                                      ROWS, 384, 128, nullptr);
    k_na<<<dim3(64, NB * NHEAD), 256, NA_SMEM>>>(qkv, rpb, na);

    // join: proj needs na (main) + t/gsum (s2)
    cudaStreamWaitEvent(0, ev_join, 0);

    // 5. fused proj (bf16) + gate + residual + LN2
    k_proj_ln<<<ROWS / 64, 256>>>(na, proj_w, proj_b, xs, t, gsum,
                                  ca1_w, ca1_b, ca2_w, ca2_b,
                                  ln2_w, ln2_b, x2, xn2);
    // 6. fc1 + gelu (bf16): 16384 x 512 x 128
    k_mma_bf16<EPI_GELU><<<dim3(8, ROWS / 64), 128>>>(xn2, fc1_w, fc1_b, h1,
                                                      ROWS, 512, 128, nullptr);
    // 7. fc2 + residual (bf16), write NCHW output
    k_mma_bf16<EPI_OUT><<<dim3(2, ROWS / 64), 128>>>(h1, fc2_w, fc2_b, out,
                                                     ROWS, 128, 512, x2);
}

// round 16
// speedup vs baseline: 1.1282x; 1.0649x over previous
#include <cuda_runtime.h>
#include <cuda_bf16.h>
#include <math.h>
#include <stdint.h>

// ---------------------------------------------------------------------------
// Problem constants
// ---------------------------------------------------------------------------
#define NB    4
#define CDIM  128
#define HWP   4096           // 64*64
#define ROWS  (NB * HWP)     // 16384
#define NHEAD 4
#define DH    32
#define KS    7

// Scratch arena layout (floats)
#define OFF_XS    0u
#define OFF_XN    2097152u            // 16384*128
#define OFF_QKV   4194304u            // len 16384*384
#define OFF_T     11010048u           // len 16384*128
#define OFF_NA    13107200u
#define OFF_X2    15204352u
#define OFF_XN2   17301504u
#define OFF_H1    19398656u           // len 16384*512
#define OFF_GSUM  27787264u           // 512
#define SCRATCH_FLOATS 27788288u

__device__ float d_scratch[SCRATCH_FLOATS];

__device__ __forceinline__ float gelu_exact(float x) {
    return 0.5f * x * (1.0f + erff(x * 0.7071067811865476f));
}

__device__ __forceinline__ uint32_t f2tf32(float f) {
    uint32_t r;
    asm("cvt.rna.tf32.f32 %0, %1;" : "=r"(r) : "f"(f));
    return r;
}

__device__ __forceinline__ void mma_tf32(float d[4], const uint32_t a[4], const uint32_t b[2]) {
    asm volatile(
        "mma.sync.aligned.m16n8k8.row.col.f32.tf32.tf32.f32 "
        "{%0,%1,%2,%3},{%4,%5,%6,%7},{%8,%9},{%0,%1,%2,%3};\n"
        : "+f"(d[0]), "+f"(d[1]), "+f"(d[2]), "+f"(d[3])
        : "r"(a[0]), "r"(a[1]), "r"(a[2]), "r"(a[3]), "r"(b[0]), "r"(b[1]));
}

__device__ __forceinline__ void mma_bf16_k16(float d[4], const uint32_t a[4], const uint32_t b[2]) {
    asm volatile(
        "mma.sync.aligned.m16n8k16.row.col.f32.bf16.bf16.f32 "
        "{%0,%1,%2,%3},{%4,%5,%6,%7},{%8,%9},{%0,%1,%2,%3};\n"
        : "+f"(d[0]), "+f"(d[1]), "+f"(d[2]), "+f"(d[3])
        : "r"(a[0]), "r"(a[1]), "r"(a[2]), "r"(a[3]), "r"(b[0]), "r"(b[1]));
}

// pack (lo, hi) floats into bf16x2 (lo in lower 16 bits = lower k index)
__device__ __forceinline__ uint32_t pack_bf16(float lo, float hi) {
    uint32_t r;
    asm("cvt.rn.bf16x2.f32 %0, %1, %2;" : "=r"(r) : "f"(hi), "f"(lo));
    return r;
}

// ---------------------------------------------------------------------------
// Kernel 1: NCHW -> NHWC transpose + LayerNorm1.  32 pixels per block.
// ---------------------------------------------------------------------------
__global__ __launch_bounds__(128)
void k_transpose_ln(const float* __restrict__ x,
                    const float* __restrict__ w, const float* __restrict__ b,
                    float* __restrict__ xs, float* __restrict__ xn,
                    float* __restrict__ gsum)
{
    __shared__ float s[32][129];
    __shared__ float smu[32], srs[32];
    int tid = threadIdx.x;
    if (blockIdx.x == 0) {
        #pragma unroll
        for (int i = 0; i < 4; i++) gsum[tid + i * 128] = 0.f;
    }
    int row0 = blockIdx.x * 32;
    int n  = row0 >> 12;
    int p0 = row0 & 4095;
    int pl = tid & 31;
    int cg = tid >> 5;       // 0..3

    #pragma unroll 4
    for (int it = 0; it < 32; it++) {
        int c = it * 4 + cg;
        s[pl][c] = x[((size_t)(n * CDIM + c) << 12) + p0 + pl];
    }
    __syncthreads();

    if (tid < 32) {
        float sum = 0.f, sq = 0.f;
        #pragma unroll 8
        for (int c = 0; c < CDIM; c++) { float v = s[tid][c]; sum += v; sq += v * v; }
        float mu  = sum * (1.0f / CDIM);
        float var = sq * (1.0f / CDIM) - mu * mu;
        smu[tid] = mu;
        srs[tid] = rsqrtf(var + 1e-5f);
    }
    __syncthreads();

    float wc = w[tid], bc = b[tid];
    #pragma unroll 4
    for (int it = 0; it < 32; it++) {
        float v = s[it][tid];
        size_t o = (size_t)(row0 + it) * CDIM + tid;
        xs[o] = v;
        xn[o] = (v - smu[it]) * srs[it] * wc + bc;
    }
}

// ---------------------------------------------------------------------------
// Epilogue helpers
// ---------------------------------------------------------------------------
#define EPI_NONE 0
#define EPI_GELU 1
#define EPI_OUT  3   // out NCHW = acc+bias + e1(x2)

template<int EPI>
__device__ __forceinline__ void epi_write(float* __restrict__ C, int row, int col,
                                          int N, float v, const float* __restrict__ e1)
{
    if (EPI == EPI_GELU) {
        C[(size_t)row * N + col] = gelu_exact(v);
    } else if (EPI == EPI_NONE) {
        C[(size_t)row * N + col] = v;
    } else { // EPI_OUT: write NCHW
        v += e1[(size_t)row * CDIM + col];
        int bn = row >> 12, p = row & 4095;
        C[((size_t)(bn * CDIM + col) << 12) + p] = v;
    }
}

// ---------------------------------------------------------------------------
// Pipelined bf16 GEMM (m16n8k16): BM=64, BN=64, BK=32.
// 256 threads / 8 warps (4 row-warps x 2 col-warps; warp tile 16x32).
// ---------------------------------------------------------------------------
template<int EPI>
__global__ __launch_bounds__(256)
void k_mma_bf16(const float* __restrict__ A, const float* __restrict__ B,
                const float* __restrict__ bias, float* __restrict__ C,
                int M, int N, int K, const float* __restrict__ e1)
{
    constexpr int BM = 64, BN = 64, BK = 32;
    __shared__ uint32_t Asp[BM][20];
    __shared__ uint32_t Bsp[BK / 2][72];

    int tid  = threadIdx.x;
    int lane = tid & 31;
    int warp = tid >> 5;
    int wm = warp & 3, wn = warp >> 2;
    int m0 = blockIdx.y * BM, n0 = blockIdx.x * BN;
    int grp = lane >> 2, qk = lane & 3;

    float d[4][4];
    #pragma unroll
    for (int nt = 0; nt < 4; nt++)
        #pragma unroll
        for (int i = 0; i < 4; i++) d[nt][i] = 0.f;

    int arow = tid >> 2, kseg = (tid & 3) * 8, apair = (tid & 3) * 4;
    int pr = tid >> 4, bc = (tid & 15) * 4;   // B: pair-row (16), col base (4 cols/thread)

    float4 pa0, pa1, pbe, pbo;

#define LDG_TILE(k0) { \
    const float* ap = A + (size_t)(m0 + arow) * K + (k0) + kseg; \
    pa0 = *(const float4*)ap; pa1 = *(const float4*)(ap + 4); \
    const float* bp = B + (size_t)((k0) + 2 * pr) * N + n0 + bc; \
    pbe = *(const float4*)bp; pbo = *(const float4*)(bp + N); }

#define STS_TILE() { \
    Asp[arow][apair+0]=pack_bf16(pa0.x,pa0.y); Asp[arow][apair+1]=pack_bf16(pa0.z,pa0.w); \
    Asp[arow][apair+2]=pack_bf16(pa1.x,pa1.y); Asp[arow][apair+3]=pack_bf16(pa1.z,pa1.w); \
    Bsp[pr][bc+0]=pack_bf16(pbe.x,pbo.x); Bsp[pr][bc+1]=pack_bf16(pbe.y,pbo.y); \
    Bsp[pr][bc+2]=pack_bf16(pbe.z,pbo.z); Bsp[pr][bc+3]=pack_bf16(pbe.w,pbo.w); }

#define MMA_TILE() { \
    _Pragma("unroll") \
    for (int ks = 0; ks < 2; ks++) { \
        int pb8 = ks * 8; \
        uint32_t af[4], bf[4][2]; \
        int r = wm * 16 + grp; \
        af[0] = Asp[r][pb8 + qk];     af[1] = Asp[r + 8][pb8 + qk]; \
        af[2] = Asp[r][pb8 + qk + 4]; af[3] = Asp[r + 8][pb8 + qk + 4]; \
        _Pragma("unroll") \
        for (int nt = 0; nt < 4; nt++) { \
            int cidx = wn * 32 + nt * 8 + grp; \
            bf[nt][0] = Bsp[pb8 + qk][cidx]; bf[nt][1] = Bsp[pb8 + qk + 4][cidx]; \
        } \
        _Pragma("unroll") \
        for (int nt = 0; nt < 4; nt++) \
            mma_bf16_k16(d[nt], af, bf[nt]); \
    } }

    LDG_TILE(0);
    STS_TILE();
    __syncthreads();
    for (int k0 = BK; k0 < K; k0 += BK) {
        LDG_TILE(k0);
        MMA_TILE();
        __syncthreads();
        STS_TILE();
        __syncthreads();
    }
    MMA_TILE();

#undef LDG_TILE
#undef STS_TILE
#undef MMA_TILE

    {
        int rbase = m0 + wm * 16 + grp;
        #pragma unroll
        for (int nt = 0; nt < 4; nt++) {
            int cbase = n0 + wn * 32 + nt * 8 + 2 * qk;
            float b0 = bias[cbase], b1 = bias[cbase + 1];
            epi_write<EPI>(C, rbase,     cbase,     N, d[nt][0] + b0, e1);
            epi_write<EPI>(C, rbase,     cbase + 1, N, d[nt][1] + b1, e1);
            epi_write<EPI>(C, rbase + 8, cbase,     N, d[nt][2] + b0, e1);
            epi_write<EPI>(C, rbase + 8, cbase + 1, N, d[nt][3] + b1, e1);
        }
    }
}

// ---------------------------------------------------------------------------
// Fused conv1 + GELU + conv2 + spatial-mean.
// 64 rows per block, 256 threads / 8 warps (4 row-warps x 2 col-warps).
// ---------------------------------------------------------------------------
__global__ __launch_bounds__(256)
void k_conv(const float* __restrict__ xn,
            const float* __restrict__ w1, const float* __restrict__ b1,
            const float* __restrict__ w2, const float* __restrict__ b2,
            float* __restrict__ tout, float* __restrict__ gsum)
{
    __shared__ uint32_t As[64][36];
    __shared__ uint32_t Bs1[32][40];
    __shared__ uint32_t St1[64][36];
    __shared__ uint32_t Bs2[32][136];

    int tid  = threadIdx.x;
    int lane = tid & 31;
    int warp = tid >> 5;
    int grp = lane >> 2, qk = lane & 3;
    int wm = warp & 3, wn = warp >> 2;
    int m0 = blockIdx.x * 64;

    // cache conv2_w (32 x 128) in smem once: 256 threads, 16 cols each
    {
        int r = tid >> 3, c0 = (tid & 7) * 16;
        #pragma unroll
        for (int i = 0; i < 4; i++) {
            float4 v = *(const float4*)(w2 + (size_t)r * 128 + c0 + i * 4);
            Bs2[r][c0 + i * 4 + 0] = f2tf32(v.x);
            Bs2[r][c0 + i * 4 + 1] = f2tf32(v.y);
            Bs2[r][c0 + i * 4 + 2] = f2tf32(v.z);
            Bs2[r][c0 + i * 4 + 3] = f2tf32(v.w);
        }
    }

    // ---- stage 1: t1 = xn @ w1 (64x32, K=128). Warp tile 16x16 ----
    float acc1[2][4];
    #pragma unroll
    for (int nt = 0; nt < 2; nt++)
        #pragma unroll
        for (int i = 0; i < 4; i++) acc1[nt][i] = 0.f;

    int arow = tid >> 2, kseg = (tid & 3) * 8;
    int b1row = tid >> 3, b1col = (tid & 7) * 4;

    for (int k0 = 0; k0 < 128; k0 += 32) {
        const float* ap = xn + (size_t)(m0 + arow) * CDIM + k0 + kseg;
        #pragma unroll
        for (int i = 0; i < 2; i++) {
            float4 v = *(const float4*)(ap + i * 4);
            As[arow][kseg + i * 4 + 0] = f2tf32(v.x);
            As[arow][kseg + i * 4 + 1] = f2tf32(v.y);
            As[arow][kseg + i * 4 + 2] = f2tf32(v.z);
            As[arow][kseg + i * 4 + 3] = f2tf32(v.w);
        }
        {
            float4 v = *(const float4*)(w1 + (size_t)(k0 + b1row) * 32 + b1col);
            Bs1[b1row][b1col + 0] = f2tf32(v.x);
            Bs1[b1row][b1col + 1] = f2tf32(v.y);
            Bs1[b1row][b1col + 2] = f2tf32(v.z);
            Bs1[b1row][b1col + 3] = f2tf32(v.w);
        }
        __syncthreads();
        #pragma unroll
        for (int kk = 0; kk < 32; kk += 8) {
            uint32_t af[4], bf[2][2];
            int r = wm * 16 + grp;
            af[0] = As[r][kk + qk];     af[1] = As[r + 8][kk + qk];
            af[2] = As[r][kk + qk + 4]; af[3] = As[r + 8][kk + qk + 4];
            #pragma unroll
            for (int nt = 0; nt < 2; nt++) {
                bf[nt][0] = Bs1[kk + qk][wn * 16 + nt * 8 + grp];
                bf[nt][1] = Bs1[kk + qk + 4][wn * 16 + nt * 8 + grp];
            }
            #pragma unroll
            for (int nt = 0; nt < 2; nt++) mma_tf32(acc1[nt], af, bf[nt]);
        }
        __syncthreads();
    }

    // stage-1 epilogue: gelu -> St1 (tf32)
    {
        int r = wm * 16 + grp;
        #pragma unroll
        for (int nt = 0; nt < 2; nt++) {
            int c = wn * 16 + nt * 8 + 2 * qk;
            float bb0 = b1[c], bb1 = b1[c + 1];
            St1[r][c]         = f2tf32(gelu_exact(acc1[nt][0] + bb0));
            St1[r][c + 1]     = f2tf32(gelu_exact(acc1[nt][1] + bb1));
            St1[r + 8][c]     = f2tf32(gelu_exact(acc1[nt][2] + bb0));
            St1[r + 8][c + 1] = f2tf32(gelu_exact(acc1[nt][3] + bb1));
        }
    }
    __syncthreads();

    // ---- stage 2: t = gelu(t1) @ w2 (64x128, K=32). Warp tile 16x64 ----
    float acc2[8][4];
    #pragma unroll
    for (int nt = 0; nt < 8; nt++)
        #pragma unroll
        for (int i = 0; i < 4; i++) acc2[nt][i] = 0.f;

    #pragma unroll
    for (int kk = 0; kk < 32; kk += 8) {
        uint32_t af[4];
        int r = wm * 16 + grp;
        af[0] = St1[r][kk + qk];     af[1] = St1[r + 8][kk + qk];
        af[2] = St1[r][kk + qk + 4]; af[3] = St1[r + 8][kk + qk + 4];
        #pragma unroll
        for (int nt = 0; nt < 8; nt++) {
            uint32_t bf[2];
            bf[0] = Bs2[kk + qk][wn * 64 + nt * 8 + grp];
            bf[1] = Bs2[kk + qk + 4][wn * 64 + nt * 8 + grp];
            mma_tf32(acc2[nt], af, bf);
        }
    }

    int n = m0 >> 12;
    int r = wm * 16 + grp;
    #pragma unroll
    for (int nt = 0; nt < 8; nt++) {
        int c = wn * 64 + nt * 8 + 2 * qk;
        float bb0 = b2[c], bb1 = b2[c + 1];
        float v0 = acc2[nt][0] + bb0, v1 = acc2[nt][1] + bb1;
        float v2 = acc2[nt][2] + bb0, v3 = acc2[nt][3] + bb1;
        size_t ro = (size_t)(m0 + r) * CDIM;
        tout[ro + c] = v0;             tout[ro + c + 1] = v1;
        tout[ro + 8 * CDIM + c] = v2;  tout[ro + 8 * CDIM + c + 1] = v3;
        float s0 = v0 + v2, s1 = v1 + v3;
        #pragma unroll
        for (int o = 4; o < 32; o <<= 1) {
            s0 += __shfl_xor_sync(0xffffffffu, s0, o);
            s1 += __shfl_xor_sync(0xffffffffu, s1, o);
        }
        if (lane < 4) {
            atomicAdd(&gsum[n * CDIM + c], s0);
            atomicAdd(&gsum[n * CDIM + c + 1], s1);
        }
    }
}

// ---------------------------------------------------------------------------
// Neighborhood attention — tensor-core tf32; sparse softmax.
// ---------------------------------------------------------------------------
#define NA_P_OFF   0
#define NA_Q_OFF   52224
#define NA_K_OFF   61440
#define NA_V_OFF   52224
#define NA_RPB_OFF 87552
#define NA_INV_OFF 88228
#define NA_SMEM    88512

__global__ __launch_bounds__(256)
void k_na(const float* __restrict__ qkv, const float* __restrict__ rpb,
          float* __restrict__ na)
{
    extern __shared__ char smem[];
    uint32_t (*P)[204]  = (uint32_t(*)[204])(smem + NA_P_OFF);
    uint32_t (*Qs)[36]  = (uint32_t(*)[36])(smem + NA_Q_OFF);
    uint32_t (*Ks)[204] = (uint32_t(*)[204])(smem + NA_K_OFF);
    uint32_t (*Vs)[40]  = (uint32_t(*)[40])(smem + NA_V_OFF);
    float* srpb = (float*)(smem + NA_RPB_OFF);
    float* sinv = (float*)(smem + NA_INV_OFF);

    int tid  = threadIdx.x;
    int lane = tid & 31;
    int warp = tid >> 5;
    int grp = lane >> 2, qk = lane & 3;

    int n = blockIdx.y >> 2;
    int h = blockIdx.y & 3;
    int i0 = (blockIdx.x >> 3) * 8, j0 = (blockIdx.x & 7) * 8;
    int wi0 = i0 - 3; wi0 = wi0 < 0 ? 0 : wi0;
    int wj0 = j0 - 3; wj0 = wj0 < 0 ? 0 : wj0;

    if (tid < 169) srpb[tid] = rpb[h * 169 + tid];

    const float* qb = qkv + (size_t)(n * HWP) * 384 + h * DH;

    #pragma unroll
    for (int idx = tid; idx < 64 * 32; idx += 256) {
        int p = idx >> 5, c = idx & 31;
        int i = i0 + (p >> 3), j = j0 + (p & 7);
        Qs[p][c] = f2tf32(qb[(size_t)(i * 64 + j) * 384 + c] * 0.17677669529663687f);
    }
    for (int idx = tid; idx < 8 * 200; idx += 256) {
        int chunk = idx / 200;
        int widx  = idx - chunk * 200;
        int c0 = chunk * 4;
        int rw = (widx * 2341) >> 15; rw = rw > 13 ? 13 : rw;
        int cw = widx - rw * 14;
        int gi = wi0 + rw; gi = gi > 63 ? 63 : gi;
        int gj = wj0 + cw; gj = gj > 63 ? 63 : gj;
        float4 v = *(const float4*)(qb + (size_t)(gi * 64 + gj) * 384 + 128 + c0);
        Ks[c0 + 0][widx] = f2tf32(v.x);
        Ks[c0 + 1][widx] = f2tf32(v.y);
        Ks[c0 + 2][widx] = f2tf32(v.z);
        Ks[c0 + 3][widx] = f2tf32(v.w);
    }
    __syncthreads();

    int mt = warp >> 1;
    int nh = warp & 1;
    int gt0 = nh ? 12 : 0;
    int ngt = nh ? 13 : 12;

    float sacc[13][4];
    #pragma unroll
    for (int t = 0; t < 13; t++)
        #pragma unroll
        for (int i = 0; i < 4; i++) sacc[t][i] = 0.f;

    #pragma unroll
    for (int kk = 0; kk < 32; kk += 8) {
        uint32_t af[4];
        int r = mt * 16 + grp;
        af[0] = Qs[r][kk + qk];     af[1] = Qs[r + 8][kk + qk];
        af[2] = Qs[r][kk + qk + 4]; af[3] = Qs[r + 8][kk + qk + 4];
        #pragma unroll
        for (int t = 0; t < 13; t++) {
            if (t < ngt) {
                int gt = gt0 + t;
                uint32_t bf[2];
                bf[0] = Ks[kk + qk][gt * 8 + grp];
                bf[1] = Ks[kk + qk + 4][gt * 8 + grp];
                mma_tf32(sacc[t], af, bf);
            }
        }
    }

    // ---- scatter: valid -> score+rpb; invalid -> 0.0f (already "exp'd") ----
    {
        int r0 = mt * 16 + grp, r1 = r0 + 8;
        int i_a = i0 + (r0 >> 3), j_a = j0 + (r0 & 7);
        int ni_a = i_a - 3; ni_a = ni_a < 0 ? 0 : (ni_a > 57 ? 57 : ni_a);
        int nj_a = j_a - 3; nj_a = nj_a < 0 ? 0 : (nj_a > 57 ? 57 : nj_a);
        int di_a = ni_a - wi0, dj_a = nj_a - wj0;
        int rb_a = (ni_a - i_a + 6) * 13 + (nj_a - j_a + 6);
        int i_b = i0 + (r1 >> 3), j_b = j0 + (r1 & 7);
        int ni_b = i_b - 3; ni_b = ni_b < 0 ? 0 : (ni_b > 57 ? 57 : ni_b);
        int nj_b = j_b - 3; nj_b = nj_b < 0 ? 0 : (nj_b > 57 ? 57 : nj_b);
        int di_b = ni_b - wi0, dj_b = nj_b - wj0;
        int rb_b = (ni_b - i_b + 6) * 13 + (nj_b - j_b + 6);

        #pragma unroll
        for (int t = 0; t < 13; t++) {
            if (t >= ngt) break;
            int gt = gt0 + t;
            #pragma unroll
            for (int cc = 0; cc < 2; cc++) {
                int col = gt * 8 + 2 * qk + cc;
                int rw = (col * 2341) >> 15;
                int cw = col - rw * 14;
                int a0 = rw - di_a, b0 = cw - dj_a;
                uint32_t v0 = ((unsigned)a0 < 7u && (unsigned)b0 < 7u)
                         ? __float_as_uint(sacc[t][cc] + srpb[rb_a + a0 * 13 + b0]) : 0u;
                P[r0][col] = v0;
                int a1 = rw - di_b, b1 = cw - dj_b;
                uint32_t v1 = ((unsigned)a1 < 7u && (unsigned)b1 < 7u)
                         ? __float_as_uint(sacc[t][2 + cc] + srpb[rb_b + a1 * 13 + b1]) : 0u;
                P[r1][col] = v1;
            }
        }
    }
    __syncthreads();

    #pragma unroll
    for (int idx = tid; idx < 200 * 32; idx += 256) {
        int widx = idx >> 5, c = idx & 31;
        int rw = (widx * 2341) >> 15; rw = rw > 13 ? 13 : rw;
        int cw = widx - rw * 14;
        int gi = wi0 + rw; gi = gi > 63 ? 63 : gi;
        int gj = wj0 + cw; gj = gj > 63 ? 63 : gj;
        Vs[widx][c] = f2tf32(qb[(size_t)(gi * 64 + gj) * 384 + 256 + c]);
    }

    // ---- sparse softmax: only the 49 valid entries per pixel ----
    {
        int p0w = warp * 8;
        #pragma unroll
        for (int pp = 0; pp < 8; pp++) {
            int p = p0w + pp;
            int i = i0 + (p >> 3), j = j0 + (p & 7);
            int ni = i - 3; ni = ni < 0 ? 0 : (ni > 57 ? 57 : ni);
            int nj = j - 3; nj = nj < 0 ? 0 : (nj > 57 ? 57 : nj);
            int wbase = (ni - wi0) * 14 + (nj - wj0);

            int a0 = (lane * 9363) >> 16, b0 = lane - a0 * 7;
            int col0 = wbase + a0 * 14 + b0;
            float v0 = __uint_as_float(P[p][col0]);
            int e1 = lane + 32;
            int a1 = (e1 * 9363) >> 16, b1 = e1 - a1 * 7;
            int col1 = wbase + a1 * 14 + b1;
            bool has1 = lane < 17;
            float v1 = has1 ? __uint_as_float(P[p][col1]) : -1e30f;

            float m = fmaxf(v0, v1);
            #pragma unroll
            for (int o = 16; o > 0; o >>= 1) m = fmaxf(m, __shfl_xor_sync(0xffffffffu, m, o));
            float ex0 = __expf(v0 - m);
            float ex1 = has1 ? __expf(v1 - m) : 0.f;
            float s = ex0 + ex1;
            #pragma unroll
            for (int o = 16; o > 0; o >>= 1) s += __shfl_xor_sync(0xffffffffu, s, o);
            P[p][col0] = f2tf32(ex0);
            if (has1) P[p][col1] = f2tf32(ex1);
            if (lane == 0) sinv[p] = 1.0f / s;
        }
    }
    __syncthreads();

    float oacc[2][4];
    #pragma unroll
    for (int nt = 0; nt < 2; nt++)
        #pragma unroll
        for (int i = 0; i < 4; i++) oacc[nt][i] = 0.f;

    int c0 = nh * 16;
    for (int kt = 0; kt < 200; kt += 8) {
        uint32_t af[4];
        int r = mt * 16 + grp;
        af[0] = P[r][kt + qk];     af[1] = P[r + 8][kt + qk];
        af[2] = P[r][kt + qk + 4]; af[3] = P[r + 8][kt + qk + 4];
        #pragma unroll
        for (int nt = 0; nt < 2; nt++) {
            uint32_t bf[2];
            bf[0] = Vs[kt + qk][c0 + nt * 8 + grp];
            bf[1] = Vs[kt + qk + 4][c0 + nt * 8 + grp];
            mma_tf32(oacc[nt], af, bf);
        }
    }

    {
        int r0 = mt * 16 + grp, r1 = r0 + 8;
        float inv0 = sinv[r0], inv1 = sinv[r1];
        int ia = i0 + (r0 >> 3), ja = j0 + (r0 & 7);
        int ib = i0 + (r1 >> 3), jb = j0 + (r1 & 7);
        size_t oa = (size_t)(n * HWP + ia * 64 + ja) * CDIM + h * DH;
        size_t ob = (size_t)(n * HWP + ib * 64 + jb) * CDIM + h * DH;
        #pragma unroll
        for (int nt = 0; nt < 2; nt++) {
            int cc0 = c0 + nt * 8 + 2 * qk;
            na[oa + cc0]     = oacc[nt][0] * inv0;
            na[oa + cc0 + 1] = oacc[nt][1] * inv0;
            na[ob + cc0]     = oacc[nt][2] * inv1;
            na[ob + cc0 + 1] = oacc[nt][3] * inv1;
        }
    }
}

// ---------------------------------------------------------------------------
// Fused proj GEMM (bf16) + gate + residual + LN2.
// BM=64, 256 threads / 8 warps (4 row-warps x 2 col-warps, warp tile 16x64).
// ---------------------------------------------------------------------------
__global__ __launch_bounds__(256)
void k_proj_ln(const float* __restrict__ A /*na*/, const float* __restrict__ B /*proj_w*/,
               const float* __restrict__ bias,
               const float* __restrict__ xs, const float* __restrict__ t,
               const float* __restrict__ gsum,
               const float* __restrict__ ca1w, const float* __restrict__ ca1b,
               const float* __restrict__ ca2w, const float* __restrict__ ca2b,
               const float* __restrict__ w2, const float* __restrict__ b2,
               float* __restrict__ x2, float* __restrict__ xn2)
{
    __shared__ union SU {
        struct { uint32_t Asp[64][20]; uint32_t Bsp[16][136]; } gm;
        float x2s[64][132];
    } sm;
    __shared__ float sgm[CDIM];
    __shared__ float sr7[7];
    __shared__ float sgarr[CDIM];

    int tid  = threadIdx.x;
    int lane = tid & 31;
    int warp = tid >> 5;
    int grp = lane >> 2, qk = lane & 3;
    int wm = warp & 3, wn = warp >> 2;
    int m0 = blockIdx.x * 64;
    int n = m0 >> 12;

    float acc[8][4];
    #pragma unroll
    for (int nt = 0; nt < 8; nt++)
        #pragma unroll
        for (int i = 0; i < 4; i++) acc[nt][i] = 0.f;

    int arow = tid >> 2, kseg = (tid & 3) * 8, apair = (tid & 3) * 4;
    int pr = tid >> 4, bc = (tid & 15) * 8;

    for (int k0 = 0; k0 < 128; k0 += 32) {
        const float* ap = A + (size_t)(m0 + arow) * CDIM + k0 + kseg;
        float4 a0 = *(const float4*)ap, a1 = *(const float4*)(ap + 4);
        sm.gm.Asp[arow][apair + 0] = pack_bf16(a0.x, a0.y);
        sm.gm.Asp[arow][apair + 1] = pack_bf16(a0.z, a0.w);
        sm.gm.Asp[arow][apair + 2] = pack_bf16(a1.x, a1.y);
        sm.gm.Asp[arow][apair + 3] = pack_bf16(a1.z, a1.w);

        const float* bp = B + (size_t)(k0 + 2 * pr) * CDIM + bc;
        #pragma unroll
        for (int i = 0; i < 2; i++) {
            float4 ev = *(const float4*)(bp + i * 4);
            float4 ov = *(const float4*)(bp + CDIM + i * 4);
            sm.gm.Bsp[pr][bc + i * 4 + 0] = pack_bf16(ev.x, ov.x);
            sm.gm.Bsp[pr][bc + i * 4 + 1] = pack_bf16(ev.y, ov.y);
            sm.gm.Bsp[pr][bc + i * 4 + 2] = pack_bf16(ev.z, ov.z);
            sm.gm.Bsp[pr][bc + i * 4 + 3] = pack_bf16(ev.w, ov.w);
        }
        __syncthreads();
        #pragma unroll
        for (int ks = 0; ks < 2; ks++) {
            int pb8 = ks * 8;
            uint32_t af[4];
            int r = wm * 16 + grp;
            af[0] = sm.gm.Asp[r][pb8 + qk];     af[1] = sm.gm.Asp[r + 8][pb8 + qk];
            af[2] = sm.gm.Asp[r][pb8 + qk + 4]; af[3] = sm.gm.Asp[r + 8][pb8 + qk + 4];
            #pragma unroll
            for (int nt = 0; nt < 8; nt++) {
                uint32_t bf[2];
                bf[0] = sm.gm.Bsp[pb8 + qk][wn * 64 + nt * 8 + grp];
                bf[1] = sm.gm.Bsp[pb8 + qk + 4][wn * 64 + nt * 8 + grp];
                mma_bf16_k16(acc[nt], af, bf);
            }
        }
        __syncthreads();
    }

    // ---- channel-attention gate in-block ----
    if (tid < CDIM) sgm[tid] = gsum[n * CDIM + tid] * (1.0f / HWP);
    __syncthreads();
    if (warp == 0) {
        float part[7];
        #pragma unroll
        for (int j = 0; j < 7; j++) part[j] = 0.f;
        #pragma unroll
        for (int k = 0; k < 4; k++) {
            int c = lane + 32 * k;
            float gv = sgm[c];
            #pragma unroll
            for (int j = 0; j < 7; j++) part[j] += gv * ca1w[c * 7 + j];
        }
        #pragma unroll
        for (int j = 0; j < 7; j++) {
            #pragma unroll
            for (int o = 16; o > 0; o >>= 1)
                part[j] += __shfl_xor_sync(0xffffffffu, part[j], o);
        }
        if (lane == 0) {
            #pragma unroll
            for (int j = 0; j < 7; j++) sr7[j] = fmaxf(part[j] + ca1b[j], 0.f);
        }
    }
    __syncthreads();
    if (tid < CDIM) {
        float s = ca2b[tid];
        #pragma unroll
        for (int j = 0; j < 7; j++) s += sr7[j] * ca2w[j * CDIM + tid];
        sgarr[tid] = (1.0f / (1.0f + expf(-s))) * 0.02f;
    }
    __syncthreads();

    // epilogue: x2 value -> smem
    {
        int r = wm * 16 + grp;
        size_t ro0 = (size_t)(m0 + r) * CDIM;
        size_t ro1 = (size_t)(m0 + r + 8) * CDIM;
        #pragma unroll
        for (int nt = 0; nt < 8; nt++) {
            int c = wn * 64 + nt * 8 + 2 * qk;
            float bb0 = bias[c], bb1 = bias[c + 1];
            float g0 = sgarr[c], g1 = sgarr[c + 1];
            sm.x2s[r][c]         = acc[nt][0] + bb0 + xs[ro0 + c]     + t[ro0 + c]     * g0;
            sm.x2s[r][c + 1]     = acc[nt][1] + bb1 + xs[ro0 + c + 1] + t[ro0 + c + 1] * g1;
            sm.x2s[r + 8][c]     = acc[nt][2] + bb0 + xs[ro1 + c]     + t[ro1 + c]     * g0;
            sm.x2s[r + 8][c + 1] = acc[nt][3] + bb1 + xs[ro1 + c + 1] + t[ro1 + c + 1] * g1;
        }
    }
    __syncthreads();

    float w2r[4], b2r[4];
    #pragma unroll
    for (int k = 0; k < 4; k++) { w2r[k] = w2[lane + 32 * k]; b2r[k] = b2[lane + 32 * k]; }

    #pragma unroll
    for (int rr = 0; rr < 8; rr++) {
        int r = warp * 8 + rr;
        float v[4];
        float sum = 0.f, sq = 0.f;
        #pragma unroll
        for (int k = 0; k < 4; k++) {
            v[k] = sm.x2s[r][lane + 32 * k];
            sum += v[k]; sq += v[k] * v[k];
        }
        #pragma unroll
        for (int o = 16; o > 0; o >>= 1) {
            sum += __shfl_xor_sync(0xffffffffu, sum, o);
            sq  += __shfl_xor_sync(0xffffffffu, sq, o);
        }
        float mu = sum * (1.0f / CDIM);
        float rs = rsqrtf(sq * (1.0f / CDIM) - mu * mu + 1e-5f);
        size_t ro = (size_t)(m0 + r) * CDIM;
        #pragma unroll
        for (int k = 0; k < 4; k++) {
            x2[ro + lane + 32 * k]  = v[k];
            xn2[ro + lane + 32 * k] = (v[k] - mu) * rs * w2r[k] + b2r[k];
        }
    }
}

// ---------------------------------------------------------------------------
// Launch — conv forked onto a second stream, overlapping qkv + NA.
// ---------------------------------------------------------------------------
extern "C" void kernel_launch(void* const* d_in, const int* in_sizes, int n_in,
                              void* d_out, int out_size)
{
    const float* x      = (const float*)d_in[0];
    const float* ln1_w  = (const float*)d_in[1];
    const float* ln1_b  = (const float*)d_in[2];
    const float* ln2_w  = (const float*)d_in[3];
    const float* ln2_b  = (const float*)d_in[4];
    const float* qkv_w  = (const float*)d_in[5];
    const float* qkv_b  = (const float*)d_in[6];
    const float* proj_w = (const float*)d_in[7];
    const float* proj_b = (const float*)d_in[8];
    const float* rpb    = (const float*)d_in[9];
    const float* conv1_w= (const float*)d_in[10];
    const float* conv1_b= (const float*)d_in[11];
    const float* conv2_w= (const float*)d_in[12];
    const float* conv2_b= (const float*)d_in[13];
    const float* ca1_w  = (const float*)d_in[14];
    const float* ca1_b  = (const float*)d_in[15];
    const float* ca2_w  = (const float*)d_in[16];
    const float* ca2_b  = (const float*)d_in[17];
    const float* fc1_w  = (const float*)d_in[18];
    const float* fc1_b  = (const float*)d_in[19];
    const float* fc2_w  = (const float*)d_in[20];
    const float* fc2_b  = (const float*)d_in[21];
    float* out = (float*)d_out;

    float* scr = nullptr;
    cudaGetSymbolAddress((void**)&scr, d_scratch);
    float* xs   = scr + OFF_XS;
    float* xn   = scr + OFF_XN;
    float* qkv  = scr + OFF_QKV;
    float* t    = scr + OFF_T;
    float* na   = scr + OFF_NA;
    float* x2   = scr + OFF_X2;
    float* xn2  = scr + OFF_XN2;
    float* h1   = scr + OFF_H1;
    float* gsum = scr + OFF_GSUM;

    cudaFuncSetAttribute(k_na, cudaFuncAttributeMaxDynamicSharedMemorySize, NA_SMEM);

    static cudaStream_t s2 = nullptr;
    static cudaEvent_t ev_fork = nullptr, ev_join = nullptr;
    if (s2 == nullptr) {
        cudaStreamCreateWithFlags(&s2, cudaStreamNonBlocking);
        cudaEventCreateWithFlags(&ev_fork, cudaEventDisableTiming);
        cudaEventCreateWithFlags(&ev_join, cudaEventDisableTiming);
    }

    // 1. transpose + LN1 (+ zero gsum)
    k_transpose_ln<<<ROWS / 32, 128>>>(x, ln1_w, ln1_b, xs, xn, gsum);

    // fork: conv path on s2 (depends only on xn/gsum)
    cudaEventRecord(ev_fork, 0);
    cudaStreamWaitEvent(s2, ev_fork, 0);
    k_conv<<<ROWS / 64, 256, 0, s2>>>(xn, conv1_w, conv1_b, conv2_w, conv2_b, t, gsum);
    cudaEventRecord(ev_join, s2);

    // main branch: qkv -> na
    k_mma_bf16<EPI_NONE><<<dim3(6, ROWS / 64), 256>>>(xn, qkv_w, qkv_b, qkv,
                                                      ROWS, 384, 128, nullptr);
    k_na<<<dim3(64, NB * NHEAD), 256, NA_SMEM>>>(qkv, rpb, na);

    // join: proj needs na (main) + t/gsum (s2)
    cudaStreamWaitEvent(0, ev_join, 0);

    // 5. fused proj (bf16) + gate + residual + LN2
    k_proj_ln<<<ROWS / 64, 256>>>(na, proj_w, proj_b, xs, t, gsum,
                                  ca1_w, ca1_b, ca2_w, ca2_b,
                                  ln2_w, ln2_b, x2, xn2);
    // 6. fc1 + gelu (bf16): 16384 x 512 x 128
    k_mma_bf16<EPI_GELU><<<dim3(8, ROWS / 64), 256>>>(xn2, fc1_w, fc1_b, h1,
                                                      ROWS, 512, 128, nullptr);
    // 7. fc2 + residual (bf16), write NCHW output
    k_mma_bf16<EPI_OUT><<<dim3(2, ROWS / 64), 256>>>(h1, fc2_w, fc2_b, out,
                                                     ROWS, 128, 512, x2);
}

// round 17
// speedup vs baseline: 1.1406x; 1.0110x over previous
#include <cuda_runtime.h>
#include <cuda_bf16.h>
#include <math.h>
#include <stdint.h>

// ---------------------------------------------------------------------------
// Problem constants
// ---------------------------------------------------------------------------
#define NB    4
#define CDIM  128
#define HWP   4096           // 64*64
#define ROWS  (NB * HWP)     // 16384
#define NHEAD 4
#define DH    32
#define KS    7

// Scratch arena layout (floats)
#define OFF_XS    0u
#define OFF_XN    2097152u            // 16384*128
#define OFF_QKV   4194304u            // len 16384*384
#define OFF_T     11010048u           // len 16384*128
#define OFF_NA    13107200u
#define OFF_X2    15204352u
#define OFF_XN2   17301504u
#define OFF_H1    19398656u           // len 16384*512
#define OFF_GSUM  27787264u           // 512
#define SCRATCH_FLOATS 27788288u

__device__ float d_scratch[SCRATCH_FLOATS];

__device__ __forceinline__ float gelu_exact(float x) {
    return 0.5f * x * (1.0f + erff(x * 0.7071067811865476f));
}

__device__ __forceinline__ uint32_t f2tf32(float f) {
    uint32_t r;
    asm("cvt.rna.tf32.f32 %0, %1;" : "=r"(r) : "f"(f));
    return r;
}

__device__ __forceinline__ void mma_tf32(float d[4], const uint32_t a[4], const uint32_t b[2]) {
    asm volatile(
        "mma.sync.aligned.m16n8k8.row.col.f32.tf32.tf32.f32 "
        "{%0,%1,%2,%3},{%4,%5,%6,%7},{%8,%9},{%0,%1,%2,%3};\n"
        : "+f"(d[0]), "+f"(d[1]), "+f"(d[2]), "+f"(d[3])
        : "r"(a[0]), "r"(a[1]), "r"(a[2]), "r"(a[3]), "r"(b[0]), "r"(b[1]));
}

__device__ __forceinline__ void mma_bf16_k16(float d[4], const uint32_t a[4], const uint32_t b[2]) {
    asm volatile(
        "mma.sync.aligned.m16n8k16.row.col.f32.bf16.bf16.f32 "
        "{%0,%1,%2,%3},{%4,%5,%6,%7},{%8,%9},{%0,%1,%2,%3};\n"
        : "+f"(d[0]), "+f"(d[1]), "+f"(d[2]), "+f"(d[3])
        : "r"(a[0]), "r"(a[1]), "r"(a[2]), "r"(a[3]), "r"(b[0]), "r"(b[1]));
}

// pack (lo, hi) floats into bf16x2 (lo in lower 16 bits = lower k index)
__device__ __forceinline__ uint32_t pack_bf16(float lo, float hi) {
    uint32_t r;
    asm("cvt.rn.bf16x2.f32 %0, %1, %2;" : "=r"(r) : "f"(hi), "f"(lo));
    return r;
}

// ---------------------------------------------------------------------------
// Kernel 1: NCHW -> NHWC transpose + LayerNorm1.  32 pixels per block.
// LN stats via warp-per-8-pixels shuffle reduction (no serial 128-LDS chain).
// ---------------------------------------------------------------------------
__global__ __launch_bounds__(128)
void k_transpose_ln(const float* __restrict__ x,
                    const float* __restrict__ w, const float* __restrict__ b,
                    float* __restrict__ xs, float* __restrict__ xn,
                    float* __restrict__ gsum)
{
    __shared__ float s[32][129];
    __shared__ float smu[32], srs[32];
    int tid = threadIdx.x;
    if (blockIdx.x == 0) {
        #pragma unroll
        for (int i = 0; i < 4; i++) gsum[tid + i * 128] = 0.f;
    }
    int row0 = blockIdx.x * 32;
    int n  = row0 >> 12;
    int p0 = row0 & 4095;
    int pl = tid & 31;
    int cg = tid >> 5;       // 0..3

    #pragma unroll 4
    for (int it = 0; it < 32; it++) {
        int c = it * 4 + cg;
        s[pl][c] = x[((size_t)(n * CDIM + c) << 12) + p0 + pl];
    }
    __syncthreads();

    // warp w handles pixels 8w..8w+7
    {
        int wp = tid >> 5, ln = tid & 31;
        #pragma unroll
        for (int pp = 0; pp < 8; pp++) {
            int p = wp * 8 + pp;
            float v0 = s[p][ln], v1 = s[p][ln + 32], v2 = s[p][ln + 64], v3 = s[p][ln + 96];
            float sum = v0 + v1 + v2 + v3;
            float sq  = v0 * v0 + v1 * v1 + v2 * v2 + v3 * v3;
            #pragma unroll
            for (int o = 16; o > 0; o >>= 1) {
                sum += __shfl_xor_sync(0xffffffffu, sum, o);
                sq  += __shfl_xor_sync(0xffffffffu, sq, o);
            }
            if (ln == 0) {
                float mu = sum * (1.0f / CDIM);
                smu[p] = mu;
                srs[p] = rsqrtf(sq * (1.0f / CDIM) - mu * mu + 1e-5f);
            }
        }
    }
    __syncthreads();

    float wc = w[tid], bc = b[tid];
    #pragma unroll 4
    for (int it = 0; it < 32; it++) {
        float v = s[it][tid];
        size_t o = (size_t)(row0 + it) * CDIM + tid;
        xs[o] = v;
        xn[o] = (v - smu[it]) * srs[it] * wc + bc;
    }
}

// ---------------------------------------------------------------------------
// Epilogue helpers
// ---------------------------------------------------------------------------
#define EPI_NONE 0
#define EPI_GELU 1
#define EPI_OUT  3   // out NCHW = acc+bias + e1(x2)

template<int EPI>
__device__ __forceinline__ void epi_write(float* __restrict__ C, int row, int col,
                                          int N, float v, const float* __restrict__ e1)
{
    if (EPI == EPI_GELU) {
        C[(size_t)row * N + col] = gelu_exact(v);
    } else if (EPI == EPI_NONE) {
        C[(size_t)row * N + col] = v;
    } else { // EPI_OUT: write NCHW
        v += e1[(size_t)row * CDIM + col];
        int bn = row >> 12, p = row & 4095;
        C[((size_t)(bn * CDIM + col) << 12) + p] = v;
    }
}

// ---------------------------------------------------------------------------
// Pipelined bf16 GEMM (m16n8k16): BM=64, BN=64, BK=32.
// 256 threads / 8 warps (4 row-warps x 2 col-warps; warp tile 16x32).
// ---------------------------------------------------------------------------
template<int EPI>
__global__ __launch_bounds__(256)
void k_mma_bf16(const float* __restrict__ A, const float* __restrict__ B,
                const float* __restrict__ bias, float* __restrict__ C,
                int M, int N, int K, const float* __restrict__ e1)
{
    constexpr int BM = 64, BN = 64, BK = 32;
    __shared__ uint32_t Asp[BM][20];
    __shared__ uint32_t Bsp[BK / 2][72];

    int tid  = threadIdx.x;
    int lane = tid & 31;
    int warp = tid >> 5;
    int wm = warp & 3, wn = warp >> 2;
    int m0 = blockIdx.y * BM, n0 = blockIdx.x * BN;
    int grp = lane >> 2, qk = lane & 3;

    float d[4][4];
    #pragma unroll
    for (int nt = 0; nt < 4; nt++)
        #pragma unroll
        for (int i = 0; i < 4; i++) d[nt][i] = 0.f;

    int arow = tid >> 2, kseg = (tid & 3) * 8, apair = (tid & 3) * 4;
    int pr = tid >> 4, bc = (tid & 15) * 4;   // B: pair-row (16), col base (4 cols/thread)

    float4 pa0, pa1, pbe, pbo;

#define LDG_TILE(k0) { \
    const float* ap = A + (size_t)(m0 + arow) * K + (k0) + kseg; \
    pa0 = *(const float4*)ap; pa1 = *(const float4*)(ap + 4); \
    const float* bp = B + (size_t)((k0) + 2 * pr) * N + n0 + bc; \
    pbe = *(const float4*)bp; pbo = *(const float4*)(bp + N); }

#define STS_TILE() { \
    Asp[arow][apair+0]=pack_bf16(pa0.x,pa0.y); Asp[arow][apair+1]=pack_bf16(pa0.z,pa0.w); \
    Asp[arow][apair+2]=pack_bf16(pa1.x,pa1.y); Asp[arow][apair+3]=pack_bf16(pa1.z,pa1.w); \
    Bsp[pr][bc+0]=pack_bf16(pbe.x,pbo.x); Bsp[pr][bc+1]=pack_bf16(pbe.y,pbo.y); \
    Bsp[pr][bc+2]=pack_bf16(pbe.z,pbo.z); Bsp[pr][bc+3]=pack_bf16(pbe.w,pbo.w); }

#define MMA_TILE() { \
    _Pragma("unroll") \
    for (int ks = 0; ks < 2; ks++) { \
        int pb8 = ks * 8; \
        uint32_t af[4], bf[4][2]; \
        int r = wm * 16 + grp; \
        af[0] = Asp[r][pb8 + qk];     af[1] = Asp[r + 8][pb8 + qk]; \
        af[2] = Asp[r][pb8 + qk + 4]; af[3] = Asp[r + 8][pb8 + qk + 4]; \
        _Pragma("unroll") \
        for (int nt = 0; nt < 4; nt++) { \
            int cidx = wn * 32 + nt * 8 + grp; \
            bf[nt][0] = Bsp[pb8 + qk][cidx]; bf[nt][1] = Bsp[pb8 + qk + 4][cidx]; \
        } \
        _Pragma("unroll") \
        for (int nt = 0; nt < 4; nt++) \
            mma_bf16_k16(d[nt], af, bf[nt]); \
    } }

    LDG_TILE(0);
    STS_TILE();
    __syncthreads();
    for (int k0 = BK; k0 < K; k0 += BK) {
        LDG_TILE(k0);
        MMA_TILE();
        __syncthreads();
        STS_TILE();
        __syncthreads();
    }
    MMA_TILE();

#undef LDG_TILE
#undef STS_TILE
#undef MMA_TILE

    {
        int rbase = m0 + wm * 16 + grp;
        #pragma unroll
        for (int nt = 0; nt < 4; nt++) {
            int cbase = n0 + wn * 32 + nt * 8 + 2 * qk;
            float b0 = bias[cbase], b1 = bias[cbase + 1];
            epi_write<EPI>(C, rbase,     cbase,     N, d[nt][0] + b0, e1);
            epi_write<EPI>(C, rbase,     cbase + 1, N, d[nt][1] + b1, e1);
            epi_write<EPI>(C, rbase + 8, cbase,     N, d[nt][2] + b0, e1);
            epi_write<EPI>(C, rbase + 8, cbase + 1, N, d[nt][3] + b1, e1);
        }
    }
}

// ---------------------------------------------------------------------------
// Fused conv1 + GELU + conv2 + spatial-mean.
// 64 rows per block, 256 threads / 8 warps (4 row-warps x 2 col-warps).
// ---------------------------------------------------------------------------
__global__ __launch_bounds__(256)
void k_conv(const float* __restrict__ xn,
            const float* __restrict__ w1, const float* __restrict__ b1,
            const float* __restrict__ w2, const float* __restrict__ b2,
            float* __restrict__ tout, float* __restrict__ gsum)
{
    __shared__ uint32_t As[64][36];
    __shared__ uint32_t Bs1[32][40];
    __shared__ uint32_t St1[64][36];
    __shared__ uint32_t Bs2[32][136];

    int tid  = threadIdx.x;
    int lane = tid & 31;
    int warp = tid >> 5;
    int grp = lane >> 2, qk = lane & 3;
    int wm = warp & 3, wn = warp >> 2;
    int m0 = blockIdx.x * 64;

    // cache conv2_w (32 x 128) in smem once: 256 threads, 16 cols each
    {
        int r = tid >> 3, c0 = (tid & 7) * 16;
        #pragma unroll
        for (int i = 0; i < 4; i++) {
            float4 v = *(const float4*)(w2 + (size_t)r * 128 + c0 + i * 4);
            Bs2[r][c0 + i * 4 + 0] = f2tf32(v.x);
            Bs2[r][c0 + i * 4 + 1] = f2tf32(v.y);
            Bs2[r][c0 + i * 4 + 2] = f2tf32(v.z);
            Bs2[r][c0 + i * 4 + 3] = f2tf32(v.w);
        }
    }

    // ---- stage 1: t1 = xn @ w1 (64x32, K=128). Warp tile 16x16 ----
    float acc1[2][4];
    #pragma unroll
    for (int nt = 0; nt < 2; nt++)
        #pragma unroll
        for (int i = 0; i < 4; i++) acc1[nt][i] = 0.f;

    int arow = tid >> 2, kseg = (tid & 3) * 8;
    int b1row = tid >> 3, b1col = (tid & 7) * 4;

    for (int k0 = 0; k0 < 128; k0 += 32) {
        const float* ap = xn + (size_t)(m0 + arow) * CDIM + k0 + kseg;
        #pragma unroll
        for (int i = 0; i < 2; i++) {
            float4 v = *(const float4*)(ap + i * 4);
            As[arow][kseg + i * 4 + 0] = f2tf32(v.x);
            As[arow][kseg + i * 4 + 1] = f2tf32(v.y);
            As[arow][kseg + i * 4 + 2] = f2tf32(v.z);
            As[arow][kseg + i * 4 + 3] = f2tf32(v.w);
        }
        {
            float4 v = *(const float4*)(w1 + (size_t)(k0 + b1row) * 32 + b1col);
            Bs1[b1row][b1col + 0] = f2tf32(v.x);
            Bs1[b1row][b1col + 1] = f2tf32(v.y);
            Bs1[b1row][b1col + 2] = f2tf32(v.z);
            Bs1[b1row][b1col + 3] = f2tf32(v.w);
        }
        __syncthreads();
        #pragma unroll
        for (int kk = 0; kk < 32; kk += 8) {
            uint32_t af[4], bf[2][2];
            int r = wm * 16 + grp;
            af[0] = As[r][kk + qk];     af[1] = As[r + 8][kk + qk];
            af[2] = As[r][kk + qk + 4]; af[3] = As[r + 8][kk + qk + 4];
            #pragma unroll
            for (int nt = 0; nt < 2; nt++) {
                bf[nt][0] = Bs1[kk + qk][wn * 16 + nt * 8 + grp];
                bf[nt][1] = Bs1[kk + qk + 4][wn * 16 + nt * 8 + grp];
            }
            #pragma unroll
            for (int nt = 0; nt < 2; nt++) mma_tf32(acc1[nt], af, bf[nt]);
        }
        __syncthreads();
    }

    // stage-1 epilogue: gelu -> St1 (tf32)
    {
        int r = wm * 16 + grp;
        #pragma unroll
        for (int nt = 0; nt < 2; nt++) {
            int c = wn * 16 + nt * 8 + 2 * qk;
            float bb0 = b1[c], bb1 = b1[c + 1];
            St1[r][c]         = f2tf32(gelu_exact(acc1[nt][0] + bb0));
            St1[r][c + 1]     = f2tf32(gelu_exact(acc1[nt][1] + bb1));
            St1[r + 8][c]     = f2tf32(gelu_exact(acc1[nt][2] + bb0));
            St1[r + 8][c + 1] = f2tf32(gelu_exact(acc1[nt][3] + bb1));
        }
    }
    __syncthreads();

    // ---- stage 2: t = gelu(t1) @ w2 (64x128, K=32). Warp tile 16x64 ----
    float acc2[8][4];
    #pragma unroll
    for (int nt = 0; nt < 8; nt++)
        #pragma unroll
        for (int i = 0; i < 4; i++) acc2[nt][i] = 0.f;

    #pragma unroll
    for (int kk = 0; kk < 32; kk += 8) {
        uint32_t af[4];
        int r = wm * 16 + grp;
        af[0] = St1[r][kk + qk];     af[1] = St1[r + 8][kk + qk];
        af[2] = St1[r][kk + qk + 4]; af[3] = St1[r + 8][kk + qk + 4];
        #pragma unroll
        for (int nt = 0; nt < 8; nt++) {
            uint32_t bf[2];
            bf[0] = Bs2[kk + qk][wn * 64 + nt * 8 + grp];
            bf[1] = Bs2[kk + qk + 4][wn * 64 + nt * 8 + grp];
            mma_tf32(acc2[nt], af, bf);
        }
    }

    int n = m0 >> 12;
    int r = wm * 16 + grp;
    #pragma unroll
    for (int nt = 0; nt < 8; nt++) {
        int c = wn * 64 + nt * 8 + 2 * qk;
        float bb0 = b2[c], bb1 = b2[c + 1];
        float v0 = acc2[nt][0] + bb0, v1 = acc2[nt][1] + bb1;
        float v2 = acc2[nt][2] + bb0, v3 = acc2[nt][3] + bb1;
        size_t ro = (size_t)(m0 + r) * CDIM;
        tout[ro + c] = v0;             tout[ro + c + 1] = v1;
        tout[ro + 8 * CDIM + c] = v2;  tout[ro + 8 * CDIM + c + 1] = v3;
        float s0 = v0 + v2, s1 = v1 + v3;
        #pragma unroll
        for (int o = 4; o < 32; o <<= 1) {
            s0 += __shfl_xor_sync(0xffffffffu, s0, o);
            s1 += __shfl_xor_sync(0xffffffffu, s1, o);
        }
        if (lane < 4) {
            atomicAdd(&gsum[n * CDIM + c], s0);
            atomicAdd(&gsum[n * CDIM + c + 1], s1);
        }
    }
}

// ---------------------------------------------------------------------------
// Neighborhood attention — tensor-core tf32; sparse softmax; V prefetched
// into registers during the S phase (hides global latency).
// ---------------------------------------------------------------------------
#define NA_P_OFF   0
#define NA_Q_OFF   52224
#define NA_K_OFF   61440
#define NA_V_OFF   52224
#define NA_RPB_OFF 87552
#define NA_INV_OFF 88228
#define NA_SMEM    88512

__global__ __launch_bounds__(256)
void k_na(const float* __restrict__ qkv, const float* __restrict__ rpb,
          float* __restrict__ na)
{
    extern __shared__ char smem[];
    uint32_t (*P)[204]  = (uint32_t(*)[204])(smem + NA_P_OFF);
    uint32_t (*Qs)[36]  = (uint32_t(*)[36])(smem + NA_Q_OFF);
    uint32_t (*Ks)[204] = (uint32_t(*)[204])(smem + NA_K_OFF);
    uint32_t (*Vs)[40]  = (uint32_t(*)[40])(smem + NA_V_OFF);
    float* srpb = (float*)(smem + NA_RPB_OFF);
    float* sinv = (float*)(smem + NA_INV_OFF);

    int tid  = threadIdx.x;
    int lane = tid & 31;
    int warp = tid >> 5;
    int grp = lane >> 2, qk = lane & 3;

    int n = blockIdx.y >> 2;
    int h = blockIdx.y & 3;
    int i0 = (blockIdx.x >> 3) * 8, j0 = (blockIdx.x & 7) * 8;
    int wi0 = i0 - 3; wi0 = wi0 < 0 ? 0 : wi0;
    int wj0 = j0 - 3; wj0 = wj0 < 0 ? 0 : wj0;

    if (tid < 169) srpb[tid] = rpb[h * 169 + tid];

    const float* qb = qkv + (size_t)(n * HWP) * 384 + h * DH;

    #pragma unroll
    for (int idx = tid; idx < 64 * 32; idx += 256) {
        int p = idx >> 5, c = idx & 31;
        int i = i0 + (p >> 3), j = j0 + (p & 7);
        Qs[p][c] = f2tf32(qb[(size_t)(i * 64 + j) * 384 + c] * 0.17677669529663687f);
    }
    for (int idx = tid; idx < 8 * 200; idx += 256) {
        int chunk = idx / 200;
        int widx  = idx - chunk * 200;
        int c0 = chunk * 4;
        int rw = (widx * 2341) >> 15; rw = rw > 13 ? 13 : rw;
        int cw = widx - rw * 14;
        int gi = wi0 + rw; gi = gi > 63 ? 63 : gi;
        int gj = wj0 + cw; gj = gj > 63 ? 63 : gj;
        float4 v = *(const float4*)(qb + (size_t)(gi * 64 + gj) * 384 + 128 + c0);
        Ks[c0 + 0][widx] = f2tf32(v.x);
        Ks[c0 + 1][widx] = f2tf32(v.y);
        Ks[c0 + 2][widx] = f2tf32(v.z);
        Ks[c0 + 3][widx] = f2tf32(v.w);
    }
    __syncthreads();

    // ---- V prefetch into registers (overlaps with S-MMA below) ----
    // thread loads V[widx][lane] for widx = warp + 8*i, i = 0..24
    float vpre[25];
    #pragma unroll
    for (int i = 0; i < 25; i++) {
        int widx = warp + 8 * i;
        int rw = (widx * 2341) >> 15; rw = rw > 13 ? 13 : rw;
        int cw = widx - rw * 14;
        int gi = wi0 + rw; gi = gi > 63 ? 63 : gi;
        int gj = wj0 + cw; gj = gj > 63 ? 63 : gj;
        vpre[i] = qb[(size_t)(gi * 64 + gj) * 384 + 256 + lane];
    }

    int mt = warp >> 1;
    int nh = warp & 1;
    int gt0 = nh ? 12 : 0;
    int ngt = nh ? 13 : 12;

    float sacc[13][4];
    #pragma unroll
    for (int t = 0; t < 13; t++)
        #pragma unroll
        for (int i = 0; i < 4; i++) sacc[t][i] = 0.f;

    #pragma unroll
    for (int kk = 0; kk < 32; kk += 8) {
        uint32_t af[4];
        int r = mt * 16 + grp;
        af[0] = Qs[r][kk + qk];     af[1] = Qs[r + 8][kk + qk];
        af[2] = Qs[r][kk + qk + 4]; af[3] = Qs[r + 8][kk + qk + 4];
        #pragma unroll
        for (int t = 0; t < 13; t++) {
            if (t < ngt) {
                int gt = gt0 + t;
                uint32_t bf[2];
                bf[0] = Ks[kk + qk][gt * 8 + grp];
                bf[1] = Ks[kk + qk + 4][gt * 8 + grp];
                mma_tf32(sacc[t], af, bf);
            }
        }
    }

    // ---- scatter: valid -> score+rpb; invalid -> 0.0f (already "exp'd") ----
    {
        int r0 = mt * 16 + grp, r1 = r0 + 8;
        int i_a = i0 + (r0 >> 3), j_a = j0 + (r0 & 7);
        int ni_a = i_a - 3; ni_a = ni_a < 0 ? 0 : (ni_a > 57 ? 57 : ni_a);
        int nj_a = j_a - 3; nj_a = nj_a < 0 ? 0 : (nj_a > 57 ? 57 : nj_a);
        int di_a = ni_a - wi0, dj_a = nj_a - wj0;
        int rb_a = (ni_a - i_a + 6) * 13 + (nj_a - j_a + 6);
        int i_b = i0 + (r1 >> 3), j_b = j0 + (r1 & 7);
        int ni_b = i_b - 3; ni_b = ni_b < 0 ? 0 : (ni_b > 57 ? 57 : ni_b);
        int nj_b = j_b - 3; nj_b = nj_b < 0 ? 0 : (nj_b > 57 ? 57 : nj_b);
        int di_b = ni_b - wi0, dj_b = nj_b - wj0;
        int rb_b = (ni_b - i_b + 6) * 13 + (nj_b - j_b + 6);

        #pragma unroll
        for (int t = 0; t < 13; t++) {
            if (t >= ngt) break;
            int gt = gt0 + t;
            #pragma unroll
            for (int cc = 0; cc < 2; cc++) {
                int col = gt * 8 + 2 * qk + cc;
                int rw = (col * 2341) >> 15;
                int cw = col - rw * 14;
                int a0 = rw - di_a, b0 = cw - dj_a;
                uint32_t v0 = ((unsigned)a0 < 7u && (unsigned)b0 < 7u)
                         ? __float_as_uint(sacc[t][cc] + srpb[rb_a + a0 * 13 + b0]) : 0u;
                P[r0][col] = v0;
                int a1 = rw - di_b, b1 = cw - dj_b;
                uint32_t v1 = ((unsigned)a1 < 7u && (unsigned)b1 < 7u)
                         ? __float_as_uint(sacc[t][2 + cc] + srpb[rb_b + a1 * 13 + b1]) : 0u;
                P[r1][col] = v1;
            }
        }
    }
    __syncthreads();   // Ks/Qs free; P ready

    // ---- store prefetched V to smem (no global latency here) ----
    #pragma unroll
    for (int i = 0; i < 25; i++)
        Vs[warp + 8 * i][lane] = f2tf32(vpre[i]);

    // ---- sparse softmax: only the 49 valid entries per pixel ----
    {
        int p0w = warp * 8;
        #pragma unroll
        for (int pp = 0; pp < 8; pp++) {
            int p = p0w + pp;
            int i = i0 + (p >> 3), j = j0 + (p & 7);
            int ni = i - 3; ni = ni < 0 ? 0 : (ni > 57 ? 57 : ni);
            int nj = j - 3; nj = nj < 0 ? 0 : (nj > 57 ? 57 : nj);
            int wbase = (ni - wi0) * 14 + (nj - wj0);

            int a0 = (lane * 9363) >> 16, b0 = lane - a0 * 7;
            int col0 = wbase + a0 * 14 + b0;
            float v0 = __uint_as_float(P[p][col0]);
            int e1 = lane + 32;
            int a1 = (e1 * 9363) >> 16, b1 = e1 - a1 * 7;
            int col1 = wbase + a1 * 14 + b1;
            bool has1 = lane < 17;
            float v1 = has1 ? __uint_as_float(P[p][col1]) : -1e30f;

            float m = fmaxf(v0, v1);
            #pragma unroll
            for (int o = 16; o > 0; o >>= 1) m = fmaxf(m, __shfl_xor_sync(0xffffffffu, m, o));
            float ex0 = __expf(v0 - m);
            float ex1 = has1 ? __expf(v1 - m) : 0.f;
            float s = ex0 + ex1;
            #pragma unroll
            for (int o = 16; o > 0; o >>= 1) s += __shfl_xor_sync(0xffffffffu, s, o);
            P[p][col0] = f2tf32(ex0);
            if (has1) P[p][col1] = f2tf32(ex1);
            if (lane == 0) sinv[p] = 1.0f / s;
        }
    }
    __syncthreads();

    float oacc[2][4];
    #pragma unroll
    for (int nt = 0; nt < 2; nt++)
        #pragma unroll
        for (int i = 0; i < 4; i++) oacc[nt][i] = 0.f;

    int c0 = nh * 16;
    #pragma unroll 5
    for (int kt = 0; kt < 200; kt += 8) {
        uint32_t af[4];
        int r = mt * 16 + grp;
        af[0] = P[r][kt + qk];     af[1] = P[r + 8][kt + qk];
        af[2] = P[r][kt + qk + 4]; af[3] = P[r + 8][kt + qk + 4];
        #pragma unroll
        for (int nt = 0; nt < 2; nt++) {
            uint32_t bf[2];
            bf[0] = Vs[kt + qk][c0 + nt * 8 + grp];
            bf[1] = Vs[kt + qk + 4][c0 + nt * 8 + grp];
            mma_tf32(oacc[nt], af, bf);
        }
    }

    {
        int r0 = mt * 16 + grp, r1 = r0 + 8;
        float inv0 = sinv[r0], inv1 = sinv[r1];
        int ia = i0 + (r0 >> 3), ja = j0 + (r0 & 7);
        int ib = i0 + (r1 >> 3), jb = j0 + (r1 & 7);
        size_t oa = (size_t)(n * HWP + ia * 64 + ja) * CDIM + h * DH;
        size_t ob = (size_t)(n * HWP + ib * 64 + jb) * CDIM + h * DH;
        #pragma unroll
        for (int nt = 0; nt < 2; nt++) {
            int cc0 = c0 + nt * 8 + 2 * qk;
            na[oa + cc0]     = oacc[nt][0] * inv0;
            na[oa + cc0 + 1] = oacc[nt][1] * inv0;
            na[ob + cc0]     = oacc[nt][2] * inv1;
            na[ob + cc0 + 1] = oacc[nt][3] * inv1;
        }
    }
}

// ---------------------------------------------------------------------------
// Fused proj GEMM (bf16) + gate + residual + LN2.
// BM=64, 256 threads / 8 warps (4 row-warps x 2 col-warps, warp tile 16x64).
// ---------------------------------------------------------------------------
__global__ __launch_bounds__(256)
void k_proj_ln(const float* __restrict__ A /*na*/, const float* __restrict__ B /*proj_w*/,
               const float* __restrict__ bias,
               const float* __restrict__ xs, const float* __restrict__ t,
               const float* __restrict__ gsum,
               const float* __restrict__ ca1w, const float* __restrict__ ca1b,
               const float* __restrict__ ca2w, const float* __restrict__ ca2b,
               const float* __restrict__ w2, const float* __restrict__ b2,
               float* __restrict__ x2, float* __restrict__ xn2)
{
    __shared__ union SU {
        struct { uint32_t Asp[64][20]; uint32_t Bsp[16][136]; } gm;
        float x2s[64][132];
    } sm;
    __shared__ float sgm[CDIM];
    __shared__ float sr7[7];
    __shared__ float sgarr[CDIM];

    int tid  = threadIdx.x;
    int lane = tid & 31;
    int warp = tid >> 5;
    int grp = lane >> 2, qk = lane & 3;
    int wm = warp & 3, wn = warp >> 2;
    int m0 = blockIdx.x * 64;
    int n = m0 >> 12;

    float acc[8][4];
    #pragma unroll
    for (int nt = 0; nt < 8; nt++)
        #pragma unroll
        for (int i = 0; i < 4; i++) acc[nt][i] = 0.f;

    int arow = tid >> 2, kseg = (tid & 3) * 8, apair = (tid & 3) * 4;
    int pr = tid >> 4, bc = (tid & 15) * 8;

    for (int k0 = 0; k0 < 128; k0 += 32) {
        const float* ap = A + (size_t)(m0 + arow) * CDIM + k0 + kseg;
        float4 a0 = *(const float4*)ap, a1 = *(const float4*)(ap + 4);
        sm.gm.Asp[arow][apair + 0] = pack_bf16(a0.x, a0.y);
        sm.gm.Asp[arow][apair + 1] = pack_bf16(a0.z, a0.w);
        sm.gm.Asp[arow][apair + 2] = pack_bf16(a1.x, a1.y);
        sm.gm.Asp[arow][apair + 3] = pack_bf16(a1.z, a1.w);

        const float* bp = B + (size_t)(k0 + 2 * pr) * CDIM + bc;
        #pragma unroll
        for (int i = 0; i < 2; i++) {
            float4 ev = *(const float4*)(bp + i * 4);
            float4 ov = *(const float4*)(bp + CDIM + i * 4);
            sm.gm.Bsp[pr][bc + i * 4 + 0] = pack_bf16(ev.x, ov.x);
            sm.gm.Bsp[pr][bc + i * 4 + 1] = pack_bf16(ev.y, ov.y);
            sm.gm.Bsp[pr][bc + i * 4 + 2] = pack_bf16(ev.z, ov.z);
            sm.gm.Bsp[pr][bc + i * 4 + 3] = pack_bf16(ev.w, ov.w);
        }
        __syncthreads();
        #pragma unroll
        for (int ks = 0; ks < 2; ks++) {
            int pb8 = ks * 8;
            uint32_t af[4];
            int r = wm * 16 + grp;
            af[0] = sm.gm.Asp[r][pb8 + qk];     af[1] = sm.gm.Asp[r + 8][pb8 + qk];
            af[2] = sm.gm.Asp[r][pb8 + qk + 4]; af[3] = sm.gm.Asp[r + 8][pb8 + qk + 4];
            #pragma unroll
            for (int nt = 0; nt < 8; nt++) {
                uint32_t bf[2];
                bf[0] = sm.gm.Bsp[pb8 + qk][wn * 64 + nt * 8 + grp];
                bf[1] = sm.gm.Bsp[pb8 + qk + 4][wn * 64 + nt * 8 + grp];
                mma_bf16_k16(acc[nt], af, bf);
            }
        }
        __syncthreads();
    }

    // ---- channel-attention gate in-block ----
    if (tid < CDIM) sgm[tid] = gsum[n * CDIM + tid] * (1.0f / HWP);
    __syncthreads();
    if (warp == 0) {
        float part[7];
        #pragma unroll
        for (int j = 0; j < 7; j++) part[j] = 0.f;
        #pragma unroll
        for (int k = 0; k < 4; k++) {
            int c = lane + 32 * k;
            float gv = sgm[c];
            #pragma unroll
            for (int j = 0; j < 7; j++) part[j] += gv * ca1w[c * 7 + j];
        }
        #pragma unroll
        for (int j = 0; j < 7; j++) {
            #pragma unroll
            for (int o = 16; o > 0; o >>= 1)
                part[j] += __shfl_xor_sync(0xffffffffu, part[j], o);
        }
        if (lane == 0) {
            #pragma unroll
            for (int j = 0; j < 7; j++) sr7[j] = fmaxf(part[j] + ca1b[j], 0.f);
        }
    }
    __syncthreads();
    if (tid < CDIM) {
        float s = ca2b[tid];
        #pragma unroll
        for (int j = 0; j < 7; j++) s += sr7[j] * ca2w[j * CDIM + tid];
        sgarr[tid] = (1.0f / (1.0f + expf(-s))) * 0.02f;
    }
    __syncthreads();

    // epilogue: x2 value -> smem
    {
        int r = wm * 16 + grp;
        size_t ro0 = (size_t)(m0 + r) * CDIM;
        size_t ro1 = (size_t)(m0 + r + 8) * CDIM;
        #pragma unroll
        for (int nt = 0; nt < 8; nt++) {
            int c = wn * 64 + nt * 8 + 2 * qk;
            float bb0 = bias[c], bb1 = bias[c + 1];
            float g0 = sgarr[c], g1 = sgarr[c + 1];
            sm.x2s[r][c]         = acc[nt][0] + bb0 + xs[ro0 + c]     + t[ro0 + c]     * g0;
            sm.x2s[r][c + 1]     = acc[nt][1] + bb1 + xs[ro0 + c + 1] + t[ro0 + c + 1] * g1;
            sm.x2s[r + 8][c]     = acc[nt][2] + bb0 + xs[ro1 + c]     + t[ro1 + c]     * g0;
            sm.x2s[r + 8][c + 1] = acc[nt][3] + bb1 + xs[ro1 + c + 1] + t[ro1 + c + 1] * g1;
        }
    }
    __syncthreads();

    float w2r[4], b2r[4];
    #pragma unroll
    for (int k = 0; k < 4; k++) { w2r[k] = w2[lane + 32 * k]; b2r[k] = b2[lane + 32 * k]; }

    #pragma unroll
    for (int rr = 0; rr < 8; rr++) {
        int r = warp * 8 + rr;
        float v[4];
        float sum = 0.f, sq = 0.f;
        #pragma unroll
        for (int k = 0; k < 4; k++) {
            v[k] = sm.x2s[r][lane + 32 * k];
            sum += v[k]; sq += v[k] * v[k];
        }
        #pragma unroll
        for (int o = 16; o > 0; o >>= 1) {
            sum += __shfl_xor_sync(0xffffffffu, sum, o);
            sq  += __shfl_xor_sync(0xffffffffu, sq, o);
        }
        float mu = sum * (1.0f / CDIM);
        float rs = rsqrtf(sq * (1.0f / CDIM) - mu * mu + 1e-5f);
        size_t ro = (size_t)(m0 + r) * CDIM;
        #pragma unroll
        for (int k = 0; k < 4; k++) {
            x2[ro + lane + 32 * k]  = v[k];
            xn2[ro + lane + 32 * k] = (v[k] - mu) * rs * w2r[k] + b2r[k];
        }
    }
}

// ---------------------------------------------------------------------------
// Launch — conv forked onto a second stream, overlapping qkv + NA.
// ---------------------------------------------------------------------------
extern "C" void kernel_launch(void* const* d_in, const int* in_sizes, int n_in,
                              void* d_out, int out_size)
{
    const float* x      = (const float*)d_in[0];
    const float* ln1_w  = (const float*)d_in[1];
    const float* ln1_b  = (const float*)d_in[2];
    const float* ln2_w  = (const float*)d_in[3];
    const float* ln2_b  = (const float*)d_in[4];
    const float* qkv_w  = (const float*)d_in[5];
    const float* qkv_b  = (const float*)d_in[6];
    const float* proj_w = (const float*)d_in[7];
    const float* proj_b = (const float*)d_in[8];
    const float* rpb    = (const float*)d_in[9];
    const float* conv1_w= (const float*)d_in[10];
    const float* conv1_b= (const float*)d_in[11];
    const float* conv2_w= (const float*)d_in[12];
    const float* conv2_b= (const float*)d_in[13];
    const float* ca1_w  = (const float*)d_in[14];
    const float* ca1_b  = (const float*)d_in[15];
    const float* ca2_w  = (const float*)d_in[16];
    const float* ca2_b  = (const float*)d_in[17];
    const float* fc1_w  = (const float*)d_in[18];
    const float* fc1_b  = (const float*)d_in[19];
    const float* fc2_w  = (const float*)d_in[20];
    const float* fc2_b  = (const float*)d_in[21];
    float* out = (float*)d_out;

    float* scr = nullptr;
    cudaGetSymbolAddress((void**)&scr, d_scratch);
    float* xs   = scr + OFF_XS;
    float* xn   = scr + OFF_XN;
    float* qkv  = scr + OFF_QKV;
    float* t    = scr + OFF_T;
    float* na   = scr + OFF_NA;
    float* x2   = scr + OFF_X2;
    float* xn2  = scr + OFF_XN2;
    float* h1   = scr + OFF_H1;
    float* gsum = scr + OFF_GSUM;

    cudaFuncSetAttribute(k_na, cudaFuncAttributeMaxDynamicSharedMemorySize, NA_SMEM);

    static cudaStream_t s2 = nullptr;
    static cudaEvent_t ev_fork = nullptr, ev_join = nullptr;
    if (s2 == nullptr) {
        cudaStreamCreateWithFlags(&s2, cudaStreamNonBlocking);
        cudaEventCreateWithFlags(&ev_fork, cudaEventDisableTiming);
        cudaEventCreateWithFlags(&ev_join, cudaEventDisableTiming);
    }

    // 1. transpose + LN1 (+ zero gsum)
    k_transpose_ln<<<ROWS / 32, 128>>>(x, ln1_w, ln1_b, xs, xn, gsum);

    // fork: conv path on s2 (depends only on xn/gsum)
    cudaEventRecord(ev_fork, 0);
    cudaStreamWaitEvent(s2, ev_fork, 0);
    k_conv<<<ROWS / 64, 256, 0, s2>>>(xn, conv1_w, conv1_b, conv2_w, conv2_b, t, gsum);
    cudaEventRecord(ev_join, s2);

    // main branch: qkv -> na
    k_mma_bf16<EPI_NONE><<<dim3(6, ROWS / 64), 256>>>(xn, qkv_w, qkv_b, qkv,
                                                      ROWS, 384, 128, nullptr);
    k_na<<<dim3(64, NB * NHEAD), 256, NA_SMEM>>>(qkv, rpb, na);

    // join: proj needs na (main) + t/gsum (s2)
    cudaStreamWaitEvent(0, ev_join, 0);

    // 5. fused proj (bf16) + gate + residual + LN2
    k_proj_ln<<<ROWS / 64, 256>>>(na, proj_w, proj_b, xs, t, gsum,
                                  ca1_w, ca1_b, ca2_w, ca2_b,
                                  ln2_w, ln2_b, x2, xn2);
    // 6. fc1 + gelu (bf16): 16384 x 512 x 128
    k_mma_bf16<EPI_GELU><<<dim3(8, ROWS / 64), 256>>>(xn2, fc1_w, fc1_b, h1,
                                                      ROWS, 512, 128, nullptr);
    // 7. fc2 + residual (bf16), write NCHW output
    k_mma_bf16<EPI_OUT><<<dim3(2, ROWS / 64), 256>>>(h1, fc2_w, fc2_b, out,
                                                     ROWS, 128, 512, x2);
}